// round 14
// baseline (speedup 1.0000x reference)
#include <cuda_runtime.h>
#include <cuda_bf16.h>
#include <cuda_fp8.h>
#include <cstdint>

#define BB 64
#define HH 2048
#define KKN 256
#define MM (KKN*BB)          // 16384 rows
#define CEPS 1e-8f
#define WSCALE 64.0f
#define RSK 128
#define SK_SCALE (1.0f/524288.0f)   // 1/(RSK*WSCALE^2)

// ---------------- scratch (static device globals; no allocation) -------------
__device__ __align__(16) float g_q[BB*HH];
__device__ float g_norm2[MM];
__device__ float g_nadd[MM];
__device__ float g_dots[MM];
__device__ float g_attn[MM];
__device__ __align__(16) float g_part[8*128*HH];  // split-K partials (Q / U+M)
__device__ __align__(16) uint8_t g_Wf8[HH*HH];    // 64*W  [o][h]
__device__ __align__(16) uint8_t g_WTf8[HH*HH];   // 64*W^T [h][o]
__device__ __align__(16) uint8_t g_Sf8[RSK*HH];
// Mext rows: 0-127 sketch M (=S*64W), 128-191 u, 192 = 64*v, 193-255 zero
__device__ __align__(16) uint8_t g_Mf8ext[256*HH];
__device__ __align__(16) uint8_t g_Af8q[128*HH];  // rows 0-63: x fp8; 64-127: 0
__device__ __align__(16) uint8_t g_Af8u[128*HH];  // rows 0-63: q; 64: 64*bias; 65-127: 0
__device__ __align__(16) uint8_t g_KBf8[(size_t)MM*HH];

// ---------------- small PTX helpers ------------------------------------------
__device__ __forceinline__ uint32_t swz128(uint32_t off){ return off ^ ((off>>3)&0x70u); }

__device__ __forceinline__ void cp16(uint32_t saddr, const void* gaddr){
  asm volatile("cp.async.cg.shared.global [%0], [%1], 16;\n" :: "r"(saddr), "l"(gaddr));
}
__device__ __forceinline__ void cp_commit(){ asm volatile("cp.async.commit_group;\n"); }
template<int N> __device__ __forceinline__ void cp_wait(){ asm volatile("cp.async.wait_group %0;\n" :: "n"(N)); }

__device__ __forceinline__ void ldmx4(uint32_t* r, uint32_t a){
  asm volatile("ldmatrix.sync.aligned.m8n8.x4.shared.b16 {%0,%1,%2,%3}, [%4];\n"
               : "=r"(r[0]), "=r"(r[1]), "=r"(r[2]), "=r"(r[3]) : "r"(a));
}
__device__ __forceinline__ void ldmx2(uint32_t* r, uint32_t a){
  asm volatile("ldmatrix.sync.aligned.m8n8.x2.shared.b16 {%0,%1}, [%2];\n"
               : "=r"(r[0]), "=r"(r[1]) : "r"(a));
}
__device__ __forceinline__ void mma16832(float* d, const uint32_t* a, const uint32_t* b){
  asm volatile("mma.sync.aligned.m16n8k32.row.col.f32.e4m3.e4m3.f32 "
               "{%0,%1,%2,%3}, {%4,%5,%6,%7}, {%8,%9}, {%0,%1,%2,%3};\n"
               : "+f"(d[0]), "+f"(d[1]), "+f"(d[2]), "+f"(d[3])
               : "r"(a[0]), "r"(a[1]), "r"(a[2]), "r"(a[3]), "r"(b[0]), "r"(b[1]));
}
__device__ __forceinline__ uint32_t f4_to_e4m3(float4 v){
  uint32_t lo = (uint32_t)__nv_cvt_float2_to_fp8x2(make_float2(v.x, v.y), __NV_SATFINITE, __NV_E4M3);
  uint32_t hi = (uint32_t)__nv_cvt_float2_to_fp8x2(make_float2(v.z, v.w), __NV_SATFINITE, __NV_E4M3);
  return lo | (hi << 16);
}
__device__ __forceinline__ uint16_t f2_to_e4m3(float a, float b){
  return (uint16_t)__nv_cvt_float2_to_fp8x2(make_float2(a, b), __NV_SATFINITE, __NV_E4M3);
}

// ---- init: S gen, x->Af8q (+zero rows 64-127), Af8u row64=64*bias,
//      Af8u rows 65-127 = 0, Mext rows 193-255 = 0 ----------------------------
__global__ void __launch_bounds__(256) kinit(const float* __restrict__ x,
                                             const float* __restrict__ bias){
  uint32_t i = blockIdx.x*256 + threadIdx.x;     // grid 256 -> 65536
  {
    uint8_t o[4];
    #pragma unroll
    for (int j = 0; j < 4; j++){
      uint32_t u = i*4 + j;
      u ^= u >> 16; u *= 0x7feb352du; u ^= u >> 15; u *= 0x846ca68bu; u ^= u >> 16;
      o[j] = (u & 1u) ? 0x38u : 0xB8u;
    }
    *(uint32_t*)(g_Sf8 + i*4) = *(uint32_t*)o;
  }
  if (i < 32768){
    float4 v = *((const float4*)x + i);
    ((uint32_t*)g_Af8q)[i] = f4_to_e4m3(v);
  } else {
    ((uint32_t*)g_Af8q)[i] = 0u;
  }
  if (i < 512){
    float4 v = *((const float4*)bias + i);
    v.x*=WSCALE; v.y*=WSCALE; v.z*=WSCALE; v.w*=WSCALE;
    ((uint32_t*)g_Af8u)[32768 + i] = f4_to_e4m3(v);   // row 64
  }
  if (i >= 33280) ((uint32_t*)g_Af8u)[i] = 0u;        // rows 65-127
  if (i < 32256) ((uint32_t*)g_Mf8ext)[98816 + i] = 0u; // Mext rows 193-255
}

// ---------------- W fp32 -> e4m3 (x64): Wf8 + transposed WTf8 ----------------
__global__ void __launch_bounds__(256) kconvW(const float* __restrict__ W){
  __shared__ float s[64][65];
  int t = threadIdx.x;
  int o0 = blockIdx.y * 64, h0 = blockIdx.x * 64;
  int rr = t >> 4, c4 = t & 15;
  #pragma unroll
  for (int i = 0; i < 4; i++){
    int r = rr + i*16;
    float4 v = *(const float4*)(W + (size_t)(o0 + r)*HH + h0 + c4*4);
    v.x*=WSCALE; v.y*=WSCALE; v.z*=WSCALE; v.w*=WSCALE;
    *(uint32_t*)(g_Wf8 + (size_t)(o0 + r)*HH + h0 + c4*4) = f4_to_e4m3(v);
    s[r][c4*4+0] = v.x; s[r][c4*4+1] = v.y; s[r][c4*4+2] = v.z; s[r][c4*4+3] = v.w;
  }
  __syncthreads();
  #pragma unroll
  for (int i = 0; i < 4; i++){
    int hr = rr + i*16;
    int og = c4*4;
    float4 v = make_float4(s[og+0][hr], s[og+1][hr], s[og+2][hr], s[og+3][hr]);
    *(uint32_t*)(g_WTf8 + (size_t)(h0 + hr)*HH + o0 + og) = f4_to_e4m3(v);
  }
}

// -------- generic fp8 128-row GEMM mainloop, param K offset + iter count -----
#define STGB 32768
#define GEMM_MAIN_P(Aptr, Bptr, N0, KOFF, NITER)                               \
  float acc[4][4][4];                                                          \
  _Pragma("unroll") for (int i = 0; i < 4; i++)                                \
    _Pragma("unroll") for (int j = 0; j < 4; j++)                              \
      _Pragma("unroll") for (int c = 0; c < 4; c++) acc[i][j][c] = 0.f;        \
  const uint32_t sbase = (uint32_t)__cvta_generic_to_shared(dsm);              \
  uint32_t soff[4];                                                            \
  const uint8_t *gA[4], *gB[4];                                                \
  _Pragma("unroll") for (int i = 0; i < 4; i++){                               \
    int id = t + i*256, r = id >> 3, c = id & 7;                               \
    soff[i] = swz128((uint32_t)(r*128 + c*16));                                \
    gA[i] = (Aptr) + (size_t)r*HH + (KOFF) + c*16;                             \
    gB[i] = (Bptr) + (size_t)((N0) + r)*HH + (KOFF) + c*16;                    \
  }                                                                            \
  auto issue = [&](int it){                                                    \
    if (it < (NITER)){                                                         \
      uint32_t sa = sbase + (it & 3)*STGB, sb = sa + 16384;                    \
      _Pragma("unroll") for (int i = 0; i < 4; i++){                           \
        cp16(sa + soff[i], gA[i] + it*128);                                    \
        cp16(sb + soff[i], gB[i] + it*128);                                    \
      }                                                                        \
    }                                                                          \
    cp_commit();                                                               \
  };                                                                           \
  issue(0); issue(1); issue(2);                                                \
  for (int it = 0; it < (NITER); ++it){                                        \
    issue(it + 3);                                                             \
    cp_wait<3>();                                                              \
    __syncthreads();                                                           \
    uint32_t sa = sbase + (it & 3)*STGB, sb = sa + 16384;                      \
    _Pragma("unroll") for (int ks = 0; ks < 4; ks++){                          \
      uint32_t af[4][4], bf[4][2];                                             \
      _Pragma("unroll") for (int mt = 0; mt < 4; mt++){                        \
        int rr = wm + mt*16 + ((lane>>3)&1)*8 + (lane&7);                      \
        int bc = ks*32 + (lane>>4)*16;                                         \
        ldmx4(af[mt], sa + swz128((uint32_t)(rr*128 + bc)));                   \
      }                                                                        \
      _Pragma("unroll") for (int nt = 0; nt < 4; nt++){                        \
        int rr = wn + nt*8 + (lane&7);                                         \
        int bc = ks*32 + ((lane>>3)&1)*16;                                     \
        ldmx2(bf[nt], sb + swz128((uint32_t)(rr*128 + bc)));                   \
      }                                                                        \
      _Pragma("unroll") for (int mt = 0; mt < 4; mt++)                        \
        _Pragma("unroll") for (int nt = 0; nt < 4; nt++)                       \
          mma16832(acc[mt][nt], af[mt], bf[nt]);                               \
    }                                                                          \
    __syncthreads();                                                           \
  }

// ------- Q partials: x @ (64W)^T, K-chunk 512, rows 0-63 only ---------------
__global__ void __launch_bounds__(256, 1) kgemmQ(){
  extern __shared__ char dsm[];
  const int t = threadIdx.x, lane = t & 31, warp = t >> 5;
  const int n0 = blockIdx.x * 128;
  const int kc = blockIdx.y;
  const int wm = (warp >> 2) * 64, wn = (warp & 3) * 32;
  GEMM_MAIN_P(g_Af8q, g_Wf8, n0, kc*512, 4)
  if (wm == 0){
    const int gid = lane >> 2, tig = lane & 3;
    float* dst = g_part + (size_t)kc*128*HH;
    #pragma unroll
    for (int mt = 0; mt < 4; mt++)
      #pragma unroll
      for (int nt = 0; nt < 4; nt++){
        int row = mt*16 + gid;
        int col = n0 + wn + nt*8 + tig*2;
        dst[row*HH + col]       = acc[mt][nt][0];
        dst[row*HH + col + 1]   = acc[mt][nt][1];
        dst[(row+8)*HH + col]   = acc[mt][nt][2];
        dst[(row+8)*HH + col+1] = acc[mt][nt][3];
      }
  }
}

// ------- fixQ: sum partials, /64 + bias -> g_q fp32 + Af8u fp8 ---------------
__global__ void __launch_bounds__(256) kfixQ(const float* __restrict__ bias){
  uint32_t idx = (blockIdx.x*256 + threadIdx.x)*2;   // grid 256 -> 131072 elems
  int col = idx & (HH-1);
  float s0 = g_part[idx]              + g_part[128*HH + idx]
           + g_part[2*128*HH + idx]   + g_part[3*128*HH + idx];
  float s1 = g_part[idx+1]            + g_part[128*HH + idx+1]
           + g_part[2*128*HH + idx+1] + g_part[3*128*HH + idx+1];
  float q0 = s0*(1.0f/WSCALE) + bias[col];
  float q1 = s1*(1.0f/WSCALE) + bias[col+1];
  *(float2*)(g_q + idx) = make_float2(q0, q1);
  *(uint16_t*)(g_Af8u + idx) = f2_to_e4m3(q0, q1);
}

// ------- U+M partials fused: z=0: [q;64b]@(64W^T); z=1: S@(64W^T) ------------
__global__ void __launch_bounds__(256, 1) kgemmUM(){
  extern __shared__ char dsm[];
  const int t = threadIdx.x, lane = t & 31, warp = t >> 5;
  const int n0 = blockIdx.x * 128;
  const int kc = blockIdx.y;
  const int z  = blockIdx.z;
  const int wm = (warp >> 2) * 64, wn = (warp & 3) * 32;
  const uint8_t* Ap = z ? g_Sf8 : g_Af8u;
  GEMM_MAIN_P(Ap, g_WTf8, n0, kc*512, 4)
  const int gid = lane >> 2, tig = lane & 3;
  float* dst = g_part + (size_t)(kc*2 + z)*128*HH;
  if (z == 1){                       // M: all 128 rows
    #pragma unroll
    for (int mt = 0; mt < 4; mt++)
      #pragma unroll
      for (int nt = 0; nt < 4; nt++){
        int row = wm + mt*16 + gid;
        int col = n0 + wn + nt*8 + tig*2;
        dst[row*HH + col]       = acc[mt][nt][0];
        dst[row*HH + col + 1]   = acc[mt][nt][1];
        dst[(row+8)*HH + col]   = acc[mt][nt][2];
        dst[(row+8)*HH + col+1] = acc[mt][nt][3];
      }
  } else if (wm == 0){               // U rows 0-63
    #pragma unroll
    for (int mt = 0; mt < 4; mt++)
      #pragma unroll
      for (int nt = 0; nt < 4; nt++){
        int row = mt*16 + gid;
        int col = n0 + wn + nt*8 + tig*2;
        dst[row*HH + col]       = acc[mt][nt][0];
        dst[row*HH + col + 1]   = acc[mt][nt][1];
        dst[(row+8)*HH + col]   = acc[mt][nt][2];
        dst[(row+8)*HH + col+1] = acc[mt][nt][3];
      }
  } else if (gid == 0){              // row 64 (v)
    #pragma unroll
    for (int nt = 0; nt < 4; nt++){
      int col = n0 + wn + nt*8 + tig*2;
      dst[64*HH + col]     = acc[0][nt][0];
      dst[64*HH + col + 1] = acc[0][nt][1];
    }
  }
}

// ---- fixUM: M partials -> Mext rows 0-127 (raw e4m3);
//      U rows 0-63 -> Mext rows 128-191 (u = sum/64);
//      U row 64    -> Mext row 192 (64v = sum/64) ----------------------------
__global__ void __launch_bounds__(256) kfixUM(){
  const uint32_t P = 128*HH;
  int bx = blockIdx.x, t = threadIdx.x;
  if (bx < 256){                        // M: 128x2048, 4 elems/thread
    uint32_t i4 = (bx*256 + t)*4;
    float4 a = *(const float4*)(g_part + 1*P + i4);
    float4 b = *(const float4*)(g_part + 3*P + i4);
    float4 c = *(const float4*)(g_part + 5*P + i4);
    float4 d = *(const float4*)(g_part + 7*P + i4);
    float4 v = make_float4(a.x+b.x+c.x+d.x, a.y+b.y+c.y+d.y,
                           a.z+b.z+c.z+d.z, a.w+b.w+c.w+d.w);
    *(uint32_t*)(g_Mf8ext + i4) = f4_to_e4m3(v);
  } else if (bx < 512){                 // u: 64x2048, 2 elems/thread
    uint32_t j = ((bx-256)*256 + t)*2;
    float s0 = g_part[j]        + g_part[2*P + j]
             + g_part[4*P + j]  + g_part[6*P + j];
    float s1 = g_part[j+1]      + g_part[2*P + j+1]
             + g_part[4*P + j+1]+ g_part[6*P + j+1];
    *(uint16_t*)(g_Mf8ext + 128*HH + j) = f2_to_e4m3(s0*(1.0f/WSCALE), s1*(1.0f/WSCALE));
  } else {                              // v row: 2048 elems, 8/thread
    uint32_t j = t*8;
    uint32_t idx = 64*HH + j;
    float4 a = make_float4(0,0,0,0), b = make_float4(0,0,0,0);
    #pragma unroll
    for (int k = 0; k < 4; k++){
      float4 pa = *(const float4*)(g_part + 2*k*P + idx);
      float4 pb = *(const float4*)(g_part + 2*k*P + idx + 4);
      a.x+=pa.x; a.y+=pa.y; a.z+=pa.z; a.w+=pa.w;
      b.x+=pb.x; b.y+=pb.y; b.z+=pb.z; b.w+=pb.w;
    }
    const float sc = 1.0f/WSCALE;       // 64v = sum/64
    a.x*=sc; a.y*=sc; a.z*=sc; a.w*=sc;
    b.x*=sc; b.y*=sc; b.z*=sc; b.w*=sc;
    uint2 o; o.x = f4_to_e4m3(a); o.y = f4_to_e4m3(b);
    *(uint2*)(g_Mf8ext + 192*HH + j) = o;
  }
}

// ---------------- KB fp32 -> e4m3 (pure streaming) ---------------------------
__global__ void __launch_bounds__(256) kconvKB(const float* __restrict__ KB){
  size_t i = ((size_t)blockIdx.x*256 + threadIdx.x)*16;   // grid 8192
  #pragma unroll
  for (int j = 0; j < 16; j += 8){
    float4 a = *(const float4*)(KB + i + j);
    float4 b = *(const float4*)(KB + i + j + 4);
    uint2 o; o.x = f4_to_e4m3(a); o.y = f4_to_e4m3(b);
    *(uint2*)(g_KBf8 + i + j) = o;
  }
}

// ---- sketch+dots GEMM: C = KBf8 @ Mext^T [16384 x 256], grid (2,128) --------
// n-half 0: rowwise sumsq of sketch cols -> g_norm2
// n-half 1: col (row&63) -> g_dots ; col 64 -> g_nadd
__global__ void __launch_bounds__(256, 1) kgemm_sk(){
  extern __shared__ char dsm[];
  __shared__ float rowsum[128];
  const int t = threadIdx.x, lane = t & 31, warp = t >> 5;
  const int m0 = blockIdx.y * 128;
  const int nh = blockIdx.x;
  const int wm = (warp >> 2) * 64, wn = (warp & 3) * 32;
  if (t < 128) rowsum[t] = 0.f;
  GEMM_MAIN_P(g_KBf8 + (size_t)m0*HH, g_Mf8ext, nh*128, 0, 16)
  const int gid = lane >> 2, tig = lane & 3;
  if (nh == 0){
    #pragma unroll
    for (int mt = 0; mt < 4; mt++){
      float s0 = 0.f, s1 = 0.f;
      #pragma unroll
      for (int nt = 0; nt < 4; nt++){
        s0 += acc[mt][nt][0]*acc[mt][nt][0] + acc[mt][nt][1]*acc[mt][nt][1];
        s1 += acc[mt][nt][2]*acc[mt][nt][2] + acc[mt][nt][3]*acc[mt][nt][3];
      }
      s0 += __shfl_xor_sync(0xffffffffu, s0, 1);
      s0 += __shfl_xor_sync(0xffffffffu, s0, 2);
      s1 += __shfl_xor_sync(0xffffffffu, s1, 1);
      s1 += __shfl_xor_sync(0xffffffffu, s1, 2);
      if (tig == 0){
        atomicAdd(&rowsum[wm + mt*16 + gid],     s0);
        atomicAdd(&rowsum[wm + mt*16 + 8 + gid], s1);
      }
    }
    __syncthreads();
    if (t < 128) g_norm2[m0 + t] = rowsum[t];
  } else {
    #pragma unroll
    for (int mt = 0; mt < 4; mt++)
      #pragma unroll
      for (int nt = 0; nt < 4; nt++){
        int row0 = wm + mt*16 + gid, row1 = row0 + 8;
        int cl = wn + nt*8 + tig*2;
        if (cl     == (row0 & 63)) g_dots[m0 + row0] = acc[mt][nt][0];
        if (cl + 1 == (row0 & 63)) g_dots[m0 + row0] = acc[mt][nt][1];
        if (cl     == (row1 & 63)) g_dots[m0 + row1] = acc[mt][nt][2];
        if (cl + 1 == (row1 & 63)) g_dots[m0 + row1] = acc[mt][nt][3];
        if (cl == 64){
          g_nadd[m0 + row0] = acc[mt][nt][0]*(2.0f/WSCALE);
          g_nadd[m0 + row1] = acc[mt][nt][2]*(2.0f/WSCALE);
        }
      }
  }
}

// ------- scores + softmax over K (q stats in-block) --------------------------
__global__ void __launch_bounds__(256) ksoftmax(const float* __restrict__ bias){
  int b = blockIdx.x, t = threadIdx.x, lane = t & 31, warp = t >> 5;
  __shared__ float sred[8], sred2[8], sred3[8];
  __shared__ float s_qn, s_qdotb, s_bn2;
  {
    const float* qr = g_q + b*HH;
    float s2 = 0.f, sb = 0.f, b2 = 0.f;
    for (int h = t; h < HH; h += 256){
      float qv = qr[h], bv = bias[h];
      s2 += qv*qv; sb += qv*bv; b2 += bv*bv;
    }
    #pragma unroll
    for (int o = 16; o; o >>= 1){
      s2 += __shfl_xor_sync(0xffffffffu, s2, o);
      sb += __shfl_xor_sync(0xffffffffu, sb, o);
      b2 += __shfl_xor_sync(0xffffffffu, b2, o);
    }
    if (lane == 0){ sred[warp] = s2; sred2[warp] = sb; sred3[warp] = b2; }
    __syncthreads();
    if (t == 0){
      float a = 0.f, c = 0.f, d = 0.f;
      #pragma unroll
      for (int i = 0; i < 8; i++){ a += sred[i]; c += sred2[i]; d += sred3[i]; }
      s_qn = fmaxf(sqrtf(a), CEPS); s_qdotb = c; s_bn2 = d;
    }
    __syncthreads();
  }
  int m = t*BB + b;
  float n2 = g_norm2[m]*SK_SCALE + g_nadd[m] + s_bn2;
  float kn = fmaxf(sqrtf(n2), CEPS);
  float sc = (g_dots[m] + s_qdotb) / (s_qn * kn);
  float v = sc;
  #pragma unroll
  for (int o = 16; o; o >>= 1) v = fmaxf(v, __shfl_xor_sync(0xffffffffu, v, o));
  __syncthreads();
  if (lane == 0) sred[warp] = v;
  __syncthreads();
  float mx = sred[0];
  #pragma unroll
  for (int i = 1; i < 8; i++) mx = fmaxf(mx, sred[i]);
  float e = expf(sc - mx);
  float s = e;
  #pragma unroll
  for (int o = 16; o; o >>= 1) s += __shfl_xor_sync(0xffffffffu, s, o);
  __syncthreads();
  if (lane == 0) sred[warp] = s;
  __syncthreads();
  float tot = 0.f;
  #pragma unroll
  for (int i = 0; i < 8; i++) tot += sred[i];
  g_attn[m] = e / tot;
}

// ------- out = x + sum_k attn[k,b] * KB[k,b,:]  (float4, 256 CTAs) -----------
__global__ void __launch_bounds__(128) kout(const float* __restrict__ x,
                                            const float* __restrict__ KB,
                                            float* __restrict__ out){
  int b = blockIdx.y;
  int h4 = blockIdx.x*128 + threadIdx.x;      // grid.x = 4
  __shared__ float at[KKN];
  at[threadIdx.x]       = g_attn[threadIdx.x*BB + b];
  at[threadIdx.x + 128] = g_attn[(threadIdx.x + 128)*BB + b];
  __syncthreads();
  const float4* p = (const float4*)KB + (size_t)b*(HH/4) + h4;
  float4 a0 = ((const float4*)x)[b*(HH/4) + h4];
  float4 a1 = make_float4(0.f,0.f,0.f,0.f);
  float4 a2 = make_float4(0.f,0.f,0.f,0.f);
  float4 a3 = make_float4(0.f,0.f,0.f,0.f);
  const size_t stride = (size_t)BB*(HH/4);
  #pragma unroll 2
  for (int k = 0; k < KKN; k += 4){
    float4 v0 = p[(k  )*stride];
    float4 v1 = p[(k+1)*stride];
    float4 v2 = p[(k+2)*stride];
    float4 v3 = p[(k+3)*stride];
    float w0 = at[k], w1 = at[k+1], w2 = at[k+2], w3 = at[k+3];
    a0.x += w0*v0.x; a0.y += w0*v0.y; a0.z += w0*v0.z; a0.w += w0*v0.w;
    a1.x += w1*v1.x; a1.y += w1*v1.y; a1.z += w1*v1.z; a1.w += w1*v1.w;
    a2.x += w2*v2.x; a2.y += w2*v2.y; a2.z += w2*v2.z; a2.w += w2*v2.w;
    a3.x += w3*v3.x; a3.y += w3*v3.y; a3.z += w3*v3.z; a3.w += w3*v3.w;
  }
  float4 r;
  r.x = a0.x + a1.x + a2.x + a3.x;
  r.y = a0.y + a1.y + a2.y + a3.y;
  r.z = a0.z + a1.z + a2.z + a3.z;
  r.w = a0.w + a1.w + a2.w + a3.w;
  ((float4*)out)[b*(HH/4) + h4] = r;
}

// ---------------- launch ------------------------------------------------------
extern "C" void kernel_launch(void* const* d_in, const int* in_sizes, int n_in,
                              void* d_out, int out_size){
  const float* x    = (const float*)d_in[0];   // [64,2048]
  const float* KB   = (const float*)d_in[1];   // [256,64,2048]
  const float* W    = (const float*)d_in[2];   // [2048,2048]
  const float* bias = (const float*)d_in[3];   // [2048]
  float* out = (float*)d_out;

  cudaFuncSetAttribute(kgemmQ,   cudaFuncAttributeMaxDynamicSharedMemorySize, 4*STGB);
  cudaFuncSetAttribute(kgemmUM,  cudaFuncAttributeMaxDynamicSharedMemorySize, 4*STGB);
  cudaFuncSetAttribute(kgemm_sk, cudaFuncAttributeMaxDynamicSharedMemorySize, 4*STGB);

  kinit<<<256, 256>>>(x, bias);
  kconvKB<<<8192, 256>>>(KB);
  kconvW<<<dim3(32, 32), 256>>>(W);
  kgemmQ<<<dim3(16, 4), 256, 4*STGB>>>();
  kfixQ<<<256, 256>>>(bias);
  kgemmUM<<<dim3(16, 4, 2), 256, 4*STGB>>>();
  kfixUM<<<513, 256>>>();
  kgemm_sk<<<dim3(2, 128), 256, 4*STGB>>>();
  ksoftmax<<<64, 256>>>(bias);
  kout<<<dim3(4, BB), 128>>>(x, KB, out);
}

// round 15
// speedup vs baseline: 1.1176x; 1.1176x over previous
#include <cuda_runtime.h>
#include <cuda_bf16.h>
#include <cuda_fp16.h>
#include <cuda_fp8.h>
#include <cstdint>

#define BB 64
#define HH 2048
#define KKN 256
#define MM (KKN*BB)          // 16384 rows
#define CEPS 1e-8f
#define WSCALE 64.0f
#define RSK 128
#define SK_SCALE (1.0f/524288.0f)   // 1/(RSK*WSCALE^2)

// ---------------- scratch (static device globals; no allocation) -------------
__device__ __align__(16) float g_q[BB*HH];
__device__ float g_norm2[MM];
__device__ float g_nadd[MM];
__device__ float g_dots[MM];
__device__ float g_attn[MM];
__device__ __align__(16) float g_part[8*128*HH];  // split-K partials (Q / U+M)
__device__ __align__(16) __half g_uh[BB*HH];      // u in half
__device__ __align__(16) __half g_vh[HH];         // v in half
__device__ __align__(16) uint8_t g_Wf8[HH*HH];    // 64*W  [o][h]
__device__ __align__(16) uint8_t g_WTf8[HH*HH];   // 64*W^T [h][o]
__device__ __align__(16) uint8_t g_Sf8[RSK*HH];
__device__ __align__(16) uint8_t g_Mf8[RSK*HH];   // sketch M
__device__ __align__(16) uint8_t g_Af8q[128*HH];  // rows 0-63: x fp8; 64-127: 0
__device__ __align__(16) uint8_t g_Af8u[128*HH];  // rows 0-63: q; 64: 64*bias; 65-127: 0
__device__ __align__(16) uint8_t g_KBf8[(size_t)MM*HH];

// ---------------- small PTX helpers ------------------------------------------
__device__ __forceinline__ uint32_t swz128(uint32_t off){ return off ^ ((off>>3)&0x70u); }

__device__ __forceinline__ void cp16(uint32_t saddr, const void* gaddr){
  asm volatile("cp.async.cg.shared.global [%0], [%1], 16;\n" :: "r"(saddr), "l"(gaddr));
}
__device__ __forceinline__ void cp_commit(){ asm volatile("cp.async.commit_group;\n"); }
template<int N> __device__ __forceinline__ void cp_wait(){ asm volatile("cp.async.wait_group %0;\n" :: "n"(N)); }

__device__ __forceinline__ void ldmx4(uint32_t* r, uint32_t a){
  asm volatile("ldmatrix.sync.aligned.m8n8.x4.shared.b16 {%0,%1,%2,%3}, [%4];\n"
               : "=r"(r[0]), "=r"(r[1]), "=r"(r[2]), "=r"(r[3]) : "r"(a));
}
__device__ __forceinline__ void ldmx2(uint32_t* r, uint32_t a){
  asm volatile("ldmatrix.sync.aligned.m8n8.x2.shared.b16 {%0,%1}, [%2];\n"
               : "=r"(r[0]), "=r"(r[1]) : "r"(a));
}
__device__ __forceinline__ void mma16832(float* d, const uint32_t* a, const uint32_t* b){
  asm volatile("mma.sync.aligned.m16n8k32.row.col.f32.e4m3.e4m3.f32 "
               "{%0,%1,%2,%3}, {%4,%5,%6,%7}, {%8,%9}, {%0,%1,%2,%3};\n"
               : "+f"(d[0]), "+f"(d[1]), "+f"(d[2]), "+f"(d[3])
               : "r"(a[0]), "r"(a[1]), "r"(a[2]), "r"(a[3]), "r"(b[0]), "r"(b[1]));
}
__device__ __forceinline__ uint32_t f4_to_e4m3(float4 v){
  uint32_t lo = (uint32_t)__nv_cvt_float2_to_fp8x2(make_float2(v.x, v.y), __NV_SATFINITE, __NV_E4M3);
  uint32_t hi = (uint32_t)__nv_cvt_float2_to_fp8x2(make_float2(v.z, v.w), __NV_SATFINITE, __NV_E4M3);
  return lo | (hi << 16);
}
__device__ __forceinline__ uint16_t f2_to_e4m3(float a, float b){
  return (uint16_t)__nv_cvt_float2_to_fp8x2(make_float2(a, b), __NV_SATFINITE, __NV_E4M3);
}
__device__ __forceinline__ __half2 e4m3x2_to_h2(uint32_t s){
  __half2_raw r = __nv_cvt_fp8x2_to_halfraw2((__nv_fp8x2_storage_t)(s & 0xffffu), __NV_E4M3);
  return *reinterpret_cast<__half2*>(&r);
}

// ---- init: S gen, x->Af8q (+zero rows 64-127), Af8u row64=64*bias, 65-127=0 -
__global__ void __launch_bounds__(256) kinit(const float* __restrict__ x,
                                             const float* __restrict__ bias){
  uint32_t i = blockIdx.x*256 + threadIdx.x;     // grid 256 -> 65536
  {
    uint8_t o[4];
    #pragma unroll
    for (int j = 0; j < 4; j++){
      uint32_t u = i*4 + j;
      u ^= u >> 16; u *= 0x7feb352du; u ^= u >> 15; u *= 0x846ca68bu; u ^= u >> 16;
      o[j] = (u & 1u) ? 0x38u : 0xB8u;
    }
    *(uint32_t*)(g_Sf8 + i*4) = *(uint32_t*)o;
  }
  if (i < 32768){
    float4 v = *((const float4*)x + i);
    ((uint32_t*)g_Af8q)[i] = f4_to_e4m3(v);
  } else {
    ((uint32_t*)g_Af8q)[i] = 0u;
  }
  if (i < 512){
    float4 v = *((const float4*)bias + i);
    v.x*=WSCALE; v.y*=WSCALE; v.z*=WSCALE; v.w*=WSCALE;
    ((uint32_t*)g_Af8u)[32768 + i] = f4_to_e4m3(v);   // row 64
  }
  if (i >= 33280) ((uint32_t*)g_Af8u)[i] = 0u;        // rows 65-127
}

// ---------------- KB fp32 -> e4m3 (pure streaming, independent) --------------
__global__ void __launch_bounds__(256) kconvKB(const float* __restrict__ KB){
  size_t i = ((size_t)blockIdx.x*256 + threadIdx.x)*16;   // grid 8192
  #pragma unroll
  for (int j = 0; j < 16; j += 8){
    float4 a = *(const float4*)(KB + i + j);
    float4 b = *(const float4*)(KB + i + j + 4);
    uint2 o; o.x = f4_to_e4m3(a); o.y = f4_to_e4m3(b);
    *(uint2*)(g_KBf8 + i + j) = o;
  }
}

// ---------------- W fp32 -> e4m3 (x64): Wf8 + transposed WTf8 ----------------
__global__ void __launch_bounds__(256) kconvW(const float* __restrict__ W){
  __shared__ float s[64][65];
  int t = threadIdx.x;
  int o0 = blockIdx.y * 64, h0 = blockIdx.x * 64;
  int rr = t >> 4, c4 = t & 15;
  #pragma unroll
  for (int i = 0; i < 4; i++){
    int r = rr + i*16;
    float4 v = *(const float4*)(W + (size_t)(o0 + r)*HH + h0 + c4*4);
    v.x*=WSCALE; v.y*=WSCALE; v.z*=WSCALE; v.w*=WSCALE;
    *(uint32_t*)(g_Wf8 + (size_t)(o0 + r)*HH + h0 + c4*4) = f4_to_e4m3(v);
    s[r][c4*4+0] = v.x; s[r][c4*4+1] = v.y; s[r][c4*4+2] = v.z; s[r][c4*4+3] = v.w;
  }
  __syncthreads();
  #pragma unroll
  for (int i = 0; i < 4; i++){
    int hr = rr + i*16;
    int og = c4*4;
    float4 v = make_float4(s[og+0][hr], s[og+1][hr], s[og+2][hr], s[og+3][hr]);
    *(uint32_t*)(g_WTf8 + (size_t)(h0 + hr)*HH + o0 + og) = f4_to_e4m3(v);
  }
}

// -------- generic fp8 128-row GEMM mainloop, param K offset + iter count -----
#define STGB 32768
#define GEMM_MAIN_P(Aptr, Bptr, N0, KOFF, NITER)                               \
  float acc[4][4][4];                                                          \
  _Pragma("unroll") for (int i = 0; i < 4; i++)                                \
    _Pragma("unroll") for (int j = 0; j < 4; j++)                              \
      _Pragma("unroll") for (int c = 0; c < 4; c++) acc[i][j][c] = 0.f;        \
  const uint32_t sbase = (uint32_t)__cvta_generic_to_shared(dsm);              \
  uint32_t soff[4];                                                            \
  const uint8_t *gA[4], *gB[4];                                                \
  _Pragma("unroll") for (int i = 0; i < 4; i++){                               \
    int id = t + i*256, r = id >> 3, c = id & 7;                               \
    soff[i] = swz128((uint32_t)(r*128 + c*16));                                \
    gA[i] = (Aptr) + (size_t)r*HH + (KOFF) + c*16;                             \
    gB[i] = (Bptr) + (size_t)((N0) + r)*HH + (KOFF) + c*16;                    \
  }                                                                            \
  auto issue = [&](int it){                                                    \
    if (it < (NITER)){                                                         \
      uint32_t sa = sbase + (it & 3)*STGB, sb = sa + 16384;                    \
      _Pragma("unroll") for (int i = 0; i < 4; i++){                           \
        cp16(sa + soff[i], gA[i] + it*128);                                    \
        cp16(sb + soff[i], gB[i] + it*128);                                    \
      }                                                                        \
    }                                                                          \
    cp_commit();                                                               \
  };                                                                           \
  issue(0); issue(1); issue(2);                                                \
  for (int it = 0; it < (NITER); ++it){                                        \
    issue(it + 3);                                                             \
    cp_wait<3>();                                                              \
    __syncthreads();                                                           \
    uint32_t sa = sbase + (it & 3)*STGB, sb = sa + 16384;                      \
    _Pragma("unroll") for (int ks = 0; ks < 4; ks++){                          \
      uint32_t af[4][4], bf[4][2];                                             \
      _Pragma("unroll") for (int mt = 0; mt < 4; mt++){                        \
        int rr = wm + mt*16 + ((lane>>3)&1)*8 + (lane&7);                      \
        int bc = ks*32 + (lane>>4)*16;                                         \
        ldmx4(af[mt], sa + swz128((uint32_t)(rr*128 + bc)));                   \
      }                                                                        \
      _Pragma("unroll") for (int nt = 0; nt < 4; nt++){                        \
        int rr = wn + nt*8 + (lane&7);                                         \
        int bc = ks*32 + ((lane>>3)&1)*16;                                     \
        ldmx2(bf[nt], sb + swz128((uint32_t)(rr*128 + bc)));                   \
      }                                                                        \
      _Pragma("unroll") for (int mt = 0; mt < 4; mt++)                        \
        _Pragma("unroll") for (int nt = 0; nt < 4; nt++)                       \
          mma16832(acc[mt][nt], af[mt], bf[nt]);                               \
    }                                                                          \
    __syncthreads();                                                           \
  }

// ------- Q partials: x @ (64W)^T, K-chunk 512, rows 0-63 only ---------------
__global__ void __launch_bounds__(256, 1) kgemmQ(){
  extern __shared__ char dsm[];
  const int t = threadIdx.x, lane = t & 31, warp = t >> 5;
  const int n0 = blockIdx.x * 128;
  const int kc = blockIdx.y;
  const int wm = (warp >> 2) * 64, wn = (warp & 3) * 32;
  GEMM_MAIN_P(g_Af8q, g_Wf8, n0, kc*512, 4)
  if (wm == 0){
    const int gid = lane >> 2, tig = lane & 3;
    float* dst = g_part + (size_t)kc*128*HH;
    #pragma unroll
    for (int mt = 0; mt < 4; mt++)
      #pragma unroll
      for (int nt = 0; nt < 4; nt++){
        int row = mt*16 + gid;
        int col = n0 + wn + nt*8 + tig*2;
        dst[row*HH + col]       = acc[mt][nt][0];
        dst[row*HH + col + 1]   = acc[mt][nt][1];
        dst[(row+8)*HH + col]   = acc[mt][nt][2];
        dst[(row+8)*HH + col+1] = acc[mt][nt][3];
      }
  }
}

// ------- fixQ: sum partials, /64 + bias -> g_q fp32 + Af8u fp8 ---------------
__global__ void __launch_bounds__(256) kfixQ(const float* __restrict__ bias){
  uint32_t idx = (blockIdx.x*256 + threadIdx.x)*2;   // grid 256 -> 131072 elems
  int col = idx & (HH-1);
  float s0 = g_part[idx]              + g_part[128*HH + idx]
           + g_part[2*128*HH + idx]   + g_part[3*128*HH + idx];
  float s1 = g_part[idx+1]            + g_part[128*HH + idx+1]
           + g_part[2*128*HH + idx+1] + g_part[3*128*HH + idx+1];
  float q0 = s0*(1.0f/WSCALE) + bias[col];
  float q1 = s1*(1.0f/WSCALE) + bias[col+1];
  *(float2*)(g_q + idx) = make_float2(q0, q1);
  *(uint16_t*)(g_Af8u + idx) = f2_to_e4m3(q0, q1);
}

// ------- U+M partials fused: z=0: [q;64b]@(64W^T); z=1: S@(64W^T) ------------
__global__ void __launch_bounds__(256, 1) kgemmUM(){
  extern __shared__ char dsm[];
  const int t = threadIdx.x, lane = t & 31, warp = t >> 5;
  const int n0 = blockIdx.x * 128;
  const int kc = blockIdx.y;
  const int z  = blockIdx.z;
  const int wm = (warp >> 2) * 64, wn = (warp & 3) * 32;
  const uint8_t* Ap = z ? g_Sf8 : g_Af8u;
  GEMM_MAIN_P(Ap, g_WTf8, n0, kc*512, 4)
  const int gid = lane >> 2, tig = lane & 3;
  float* dst = g_part + (size_t)(kc*2 + z)*128*HH;
  if (z == 1){                       // M: all 128 rows
    #pragma unroll
    for (int mt = 0; mt < 4; mt++)
      #pragma unroll
      for (int nt = 0; nt < 4; nt++){
        int row = wm + mt*16 + gid;
        int col = n0 + wn + nt*8 + tig*2;
        dst[row*HH + col]       = acc[mt][nt][0];
        dst[row*HH + col + 1]   = acc[mt][nt][1];
        dst[(row+8)*HH + col]   = acc[mt][nt][2];
        dst[(row+8)*HH + col+1] = acc[mt][nt][3];
      }
  } else if (wm == 0){               // U rows 0-63
    #pragma unroll
    for (int mt = 0; mt < 4; mt++)
      #pragma unroll
      for (int nt = 0; nt < 4; nt++){
        int row = mt*16 + gid;
        int col = n0 + wn + nt*8 + tig*2;
        dst[row*HH + col]       = acc[mt][nt][0];
        dst[row*HH + col + 1]   = acc[mt][nt][1];
        dst[(row+8)*HH + col]   = acc[mt][nt][2];
        dst[(row+8)*HH + col+1] = acc[mt][nt][3];
      }
  } else if (gid == 0){              // row 64 (v)
    #pragma unroll
    for (int nt = 0; nt < 4; nt++){
      int col = n0 + wn + nt*8 + tig*2;
      dst[64*HH + col]     = acc[0][nt][0];
      dst[64*HH + col + 1] = acc[0][nt][1];
    }
  }
}

// ---- fixUM: M partials (slabs 1,3,5,7) -> Mf8 e4m3;
//      U rows 0-63 (slabs 0,2,4,6) -> g_uh (u = sum/64);
//      U row 64 -> g_vh (v = sum/4096) ---------------------------------------
__global__ void __launch_bounds__(256) kfixUM(){
  const uint32_t P = 128*HH;
  int bx = blockIdx.x, t = threadIdx.x;
  if (bx < 256){                        // M: 128x2048, 4 elems/thread
    uint32_t i4 = (bx*256 + t)*4;
    float4 a = *(const float4*)(g_part + 1*P + i4);
    float4 b = *(const float4*)(g_part + 3*P + i4);
    float4 c = *(const float4*)(g_part + 5*P + i4);
    float4 d = *(const float4*)(g_part + 7*P + i4);
    float4 v = make_float4(a.x+b.x+c.x+d.x, a.y+b.y+c.y+d.y,
                           a.z+b.z+c.z+d.z, a.w+b.w+c.w+d.w);
    *(uint32_t*)(g_Mf8 + i4) = f4_to_e4m3(v);
  } else if (bx < 512){                 // u: 64x2048, 2 elems/thread
    uint32_t j = ((bx-256)*256 + t)*2;
    float s0 = g_part[j]        + g_part[2*P + j]
             + g_part[4*P + j]  + g_part[6*P + j];
    float s1 = g_part[j+1]      + g_part[2*P + j+1]
             + g_part[4*P + j+1]+ g_part[6*P + j+1];
    *(__half2*)(g_uh + j) = __floats2half2_rn(s0*(1.0f/WSCALE), s1*(1.0f/WSCALE));
  } else {                              // v row: 2048 elems, 8/thread
    uint32_t j = t*8;
    uint32_t idx = 64*HH + j;
    float4 a = make_float4(0,0,0,0), b = make_float4(0,0,0,0);
    #pragma unroll
    for (int k = 0; k < 4; k++){
      float4 pa = *(const float4*)(g_part + 2*k*P + idx);
      float4 pb = *(const float4*)(g_part + 2*k*P + idx + 4);
      a.x+=pa.x; a.y+=pa.y; a.z+=pa.z; a.w+=pa.w;
      b.x+=pb.x; b.y+=pb.y; b.z+=pb.z; b.w+=pb.w;
    }
    const float sc = 1.0f/(WSCALE*WSCALE);   // v = sum/4096
    __half2 h[4];
    h[0] = __floats2half2_rn(a.x*sc, a.y*sc);
    h[1] = __floats2half2_rn(a.z*sc, a.w*sc);
    h[2] = __floats2half2_rn(b.x*sc, b.y*sc);
    h[3] = __floats2half2_rn(b.z*sc, b.w*sc);
    *(uint4*)(g_vh + j) = *(uint4*)h;
  }
}

// --- dots[m] = fp8(kb).u ; nadd[m] = 2 fp8(kb).v  (warp per row) -------------
__global__ void __launch_bounds__(256) kdots(){
  int row  = blockIdx.x*8 + (threadIdx.x >> 5);
  int lane = threadIdx.x & 31;
  int b = row & (BB-1);
  const uint2* kp = (const uint2*)(g_KBf8 + (size_t)row*HH);
  const uint4* up = (const uint4*)(g_uh + b*HH);
  const uint4* vp = (const uint4*)g_vh;
  float d = 0.f, e = 0.f;
  #pragma unroll
  for (int j = 0; j < 8; j++){
    uint2 kb = kp[j*32 + lane];
    uint4 uu = up[j*32 + lane];
    uint4 vv = vp[j*32 + lane];
    __half2 k0 = e4m3x2_to_h2(kb.x),       k1 = e4m3x2_to_h2(kb.x >> 16);
    __half2 k2 = e4m3x2_to_h2(kb.y),       k3 = e4m3x2_to_h2(kb.y >> 16);
    float2 p0 = __half22float2(__hmul2(k0, *(__half2*)&uu.x));
    float2 p1 = __half22float2(__hmul2(k1, *(__half2*)&uu.y));
    float2 p2 = __half22float2(__hmul2(k2, *(__half2*)&uu.z));
    float2 p3 = __half22float2(__hmul2(k3, *(__half2*)&uu.w));
    d += (p0.x+p0.y) + (p1.x+p1.y) + (p2.x+p2.y) + (p3.x+p3.y);
    float2 q0 = __half22float2(__hmul2(k0, *(__half2*)&vv.x));
    float2 q1 = __half22float2(__hmul2(k1, *(__half2*)&vv.y));
    float2 q2 = __half22float2(__hmul2(k2, *(__half2*)&vv.z));
    float2 q3 = __half22float2(__hmul2(k3, *(__half2*)&vv.w));
    e += (q0.x+q0.y) + (q1.x+q1.y) + (q2.x+q2.y) + (q3.x+q3.y);
  }
  #pragma unroll
  for (int o = 16; o; o >>= 1){
    d += __shfl_xor_sync(0xffffffffu, d, o);
    e += __shfl_xor_sync(0xffffffffu, e, o);
  }
  if (lane == 0){
    g_dots[row] = d;
    g_nadd[row] = 2.f * e;
  }
}

// --------- sketch GEMM: C = KBf8 @ Mf8^T [16384x128], rowwise sumsq ----------
__global__ void __launch_bounds__(256, 1) kgemm_sk(){
  extern __shared__ char dsm[];
  __shared__ float rowsum[128];
  const int t = threadIdx.x, lane = t & 31, warp = t >> 5;
  const int m0 = blockIdx.x * 128;
  const int wm = (warp >> 2) * 64, wn = (warp & 3) * 32;
  if (t < 128) rowsum[t] = 0.f;
  GEMM_MAIN_P(g_KBf8 + (size_t)m0*HH, g_Mf8, 0, 0, 16)
  const int gid = lane >> 2, tig = lane & 3;
  #pragma unroll
  for (int mt = 0; mt < 4; mt++){
    float s0 = 0.f, s1 = 0.f;
    #pragma unroll
    for (int nt = 0; nt < 4; nt++){
      s0 += acc[mt][nt][0]*acc[mt][nt][0] + acc[mt][nt][1]*acc[mt][nt][1];
      s1 += acc[mt][nt][2]*acc[mt][nt][2] + acc[mt][nt][3]*acc[mt][nt][3];
    }
    s0 += __shfl_xor_sync(0xffffffffu, s0, 1);
    s0 += __shfl_xor_sync(0xffffffffu, s0, 2);
    s1 += __shfl_xor_sync(0xffffffffu, s1, 1);
    s1 += __shfl_xor_sync(0xffffffffu, s1, 2);
    if (tig == 0){
      atomicAdd(&rowsum[wm + mt*16 + gid],     s0);
      atomicAdd(&rowsum[wm + mt*16 + 8 + gid], s1);
    }
  }
  __syncthreads();
  if (t < 128) g_norm2[m0 + t] = rowsum[t];
}

// ------- scores + softmax over K (q stats in-block) --------------------------
__global__ void __launch_bounds__(256) ksoftmax(const float* __restrict__ bias){
  int b = blockIdx.x, t = threadIdx.x, lane = t & 31, warp = t >> 5;
  __shared__ float sred[8], sred2[8], sred3[8];
  __shared__ float s_qn, s_qdotb, s_bn2;
  {
    const float* qr = g_q + b*HH;
    float s2 = 0.f, sb = 0.f, b2 = 0.f;
    for (int h = t; h < HH; h += 256){
      float qv = qr[h], bv = bias[h];
      s2 += qv*qv; sb += qv*bv; b2 += bv*bv;
    }
    #pragma unroll
    for (int o = 16; o; o >>= 1){
      s2 += __shfl_xor_sync(0xffffffffu, s2, o);
      sb += __shfl_xor_sync(0xffffffffu, sb, o);
      b2 += __shfl_xor_sync(0xffffffffu, b2, o);
    }
    if (lane == 0){ sred[warp] = s2; sred2[warp] = sb; sred3[warp] = b2; }
    __syncthreads();
    if (t == 0){
      float a = 0.f, c = 0.f, d = 0.f;
      #pragma unroll
      for (int i = 0; i < 8; i++){ a += sred[i]; c += sred2[i]; d += sred3[i]; }
      s_qn = fmaxf(sqrtf(a), CEPS); s_qdotb = c; s_bn2 = d;
    }
    __syncthreads();
  }
  int m = t*BB + b;
  float n2 = g_norm2[m]*SK_SCALE + g_nadd[m] + s_bn2;
  float kn = fmaxf(sqrtf(n2), CEPS);
  float sc = (g_dots[m] + s_qdotb) / (s_qn * kn);
  float v = sc;
  #pragma unroll
  for (int o = 16; o; o >>= 1) v = fmaxf(v, __shfl_xor_sync(0xffffffffu, v, o));
  __syncthreads();
  if (lane == 0) sred[warp] = v;
  __syncthreads();
  float mx = sred[0];
  #pragma unroll
  for (int i = 1; i < 8; i++) mx = fmaxf(mx, sred[i]);
  float e = expf(sc - mx);
  float s = e;
  #pragma unroll
  for (int o = 16; o; o >>= 1) s += __shfl_xor_sync(0xffffffffu, s, o);
  __syncthreads();
  if (lane == 0) sred[warp] = s;
  __syncthreads();
  float tot = 0.f;
  #pragma unroll
  for (int i = 0; i < 8; i++) tot += sred[i];
  g_attn[m] = e / tot;
}

// ------- out = x + sum_k attn[k,b] * KB[k,b,:]  (float4, 256 CTAs) -----------
__global__ void __launch_bounds__(128) kout(const float* __restrict__ x,
                                            const float* __restrict__ KB,
                                            float* __restrict__ out){
  int b = blockIdx.y;
  int h4 = blockIdx.x*128 + threadIdx.x;      // grid.x = 4
  __shared__ float at[KKN];
  at[threadIdx.x]       = g_attn[threadIdx.x*BB + b];
  at[threadIdx.x + 128] = g_attn[(threadIdx.x + 128)*BB + b];
  __syncthreads();
  const float4* p = (const float4*)KB + (size_t)b*(HH/4) + h4;
  float4 a0 = ((const float4*)x)[b*(HH/4) + h4];
  float4 a1 = make_float4(0.f,0.f,0.f,0.f);
  float4 a2 = make_float4(0.f,0.f,0.f,0.f);
  float4 a3 = make_float4(0.f,0.f,0.f,0.f);
  const size_t stride = (size_t)BB*(HH/4);
  #pragma unroll 2
  for (int k = 0; k < KKN; k += 4){
    float4 v0 = p[(k  )*stride];
    float4 v1 = p[(k+1)*stride];
    float4 v2 = p[(k+2)*stride];
    float4 v3 = p[(k+3)*stride];
    float w0 = at[k], w1 = at[k+1], w2 = at[k+2], w3 = at[k+3];
    a0.x += w0*v0.x; a0.y += w0*v0.y; a0.z += w0*v0.z; a0.w += w0*v0.w;
    a1.x += w1*v1.x; a1.y += w1*v1.y; a1.z += w1*v1.z; a1.w += w1*v1.w;
    a2.x += w2*v2.x; a2.y += w2*v2.y; a2.z += w2*v2.z; a2.w += w2*v2.w;
    a3.x += w3*v3.x; a3.y += w3*v3.y; a3.z += w3*v3.z; a3.w += w3*v3.w;
  }
  float4 r;
  r.x = a0.x + a1.x + a2.x + a3.x;
  r.y = a0.y + a1.y + a2.y + a3.y;
  r.z = a0.z + a1.z + a2.z + a3.z;
  r.w = a0.w + a1.w + a2.w + a3.w;
  ((float4*)out)[b*(HH/4) + h4] = r;
}

// ---------------- launch ------------------------------------------------------
extern "C" void kernel_launch(void* const* d_in, const int* in_sizes, int n_in,
                              void* d_out, int out_size){
  const float* x    = (const float*)d_in[0];   // [64,2048]
  const float* KB   = (const float*)d_in[1];   // [256,64,2048]
  const float* W    = (const float*)d_in[2];   // [2048,2048]
  const float* bias = (const float*)d_in[3];   // [2048]
  float* out = (float*)d_out;

  cudaFuncSetAttribute(kgemmQ,   cudaFuncAttributeMaxDynamicSharedMemorySize, 4*STGB);
  cudaFuncSetAttribute(kgemmUM,  cudaFuncAttributeMaxDynamicSharedMemorySize, 4*STGB);
  cudaFuncSetAttribute(kgemm_sk, cudaFuncAttributeMaxDynamicSharedMemorySize, 4*STGB);

  kinit<<<256, 256>>>(x, bias);
  kconvKB<<<8192, 256>>>(KB);
  kconvW<<<dim3(32, 32), 256>>>(W);
  kgemmQ<<<dim3(16, 4), 256, 4*STGB>>>();
  kfixQ<<<256, 256>>>(bias);
  kgemmUM<<<dim3(16, 4, 2), 256, 4*STGB>>>();
  kfixUM<<<513, 256>>>();
  kdots<<<MM/8, 256>>>();
  kgemm_sk<<<128, 256, 4*STGB>>>();
  ksoftmax<<<64, 256>>>(bias);
  kout<<<dim3(4, BB), 128>>>(x, KB, out);
}

// round 16
// speedup vs baseline: 1.3257x; 1.1861x over previous
#include <cuda_runtime.h>
#include <cuda_bf16.h>
#include <cuda_fp16.h>
#include <cuda_fp8.h>
#include <cstdint>

#define BB 64
#define HH 2048
#define KKN 256
#define MM (KKN*BB)          // 16384 rows
#define CEPS 1e-8f
#define WSCALE 64.0f
#define RSK 63               // sketch rows (packed into UM GEMM rows 65-127)
#define SK_SCALE (1.0f/258048.0f)   // 1/(RSK*WSCALE^2) = 1/(63*4096)

// ---------------- scratch (static device globals; no allocation) -------------
__device__ __align__(16) float g_q[BB*HH];
__device__ float g_norm2[MM];
__device__ float g_nadd[MM];
__device__ float g_dots[MM];
__device__ float g_attn[MM];
__device__ __align__(16) float g_part[4*128*HH];  // split-K partials (Q / UM)
__device__ __align__(16) __half g_uh[BB*HH];      // u in half
__device__ __align__(16) __half g_vh[HH];         // v in half
__device__ __align__(16) uint8_t g_Wf8[HH*HH];    // 64*W  [o][h]
__device__ __align__(16) uint8_t g_WTf8[HH*HH];   // 64*W^T [h][o]
__device__ __align__(16) uint8_t g_Mf8[64*HH];    // sketch M rows 0-62; row 63 = 0
__device__ __align__(16) uint8_t g_Af8q[64*HH];   // x fp8
__device__ __align__(16) uint8_t g_Af8u[128*HH];  // 0-63: q; 64: 64*bias; 65-127: S
__device__ __align__(16) uint8_t g_KBf8[(size_t)MM*HH];

// ---------------- small PTX helpers ------------------------------------------
__device__ __forceinline__ uint32_t swz128(uint32_t off){ return off ^ ((off>>3)&0x70u); }

__device__ __forceinline__ void cp16(uint32_t saddr, const void* gaddr){
  asm volatile("cp.async.cg.shared.global [%0], [%1], 16;\n" :: "r"(saddr), "l"(gaddr));
}
__device__ __forceinline__ void cp_commit(){ asm volatile("cp.async.commit_group;\n"); }
template<int N> __device__ __forceinline__ void cp_wait(){ asm volatile("cp.async.wait_group %0;\n" :: "n"(N)); }

__device__ __forceinline__ void ldmx4(uint32_t* r, uint32_t a){
  asm volatile("ldmatrix.sync.aligned.m8n8.x4.shared.b16 {%0,%1,%2,%3}, [%4];\n"
               : "=r"(r[0]), "=r"(r[1]), "=r"(r[2]), "=r"(r[3]) : "r"(a));
}
__device__ __forceinline__ void ldmx2(uint32_t* r, uint32_t a){
  asm volatile("ldmatrix.sync.aligned.m8n8.x2.shared.b16 {%0,%1}, [%2];\n"
               : "=r"(r[0]), "=r"(r[1]) : "r"(a));
}
__device__ __forceinline__ void mma16832(float* d, const uint32_t* a, const uint32_t* b){
  asm volatile("mma.sync.aligned.m16n8k32.row.col.f32.e4m3.e4m3.f32 "
               "{%0,%1,%2,%3}, {%4,%5,%6,%7}, {%8,%9}, {%0,%1,%2,%3};\n"
               : "+f"(d[0]), "+f"(d[1]), "+f"(d[2]), "+f"(d[3])
               : "r"(a[0]), "r"(a[1]), "r"(a[2]), "r"(a[3]), "r"(b[0]), "r"(b[1]));
}
__device__ __forceinline__ uint32_t f4_to_e4m3(float4 v){
  uint32_t lo = (uint32_t)__nv_cvt_float2_to_fp8x2(make_float2(v.x, v.y), __NV_SATFINITE, __NV_E4M3);
  uint32_t hi = (uint32_t)__nv_cvt_float2_to_fp8x2(make_float2(v.z, v.w), __NV_SATFINITE, __NV_E4M3);
  return lo | (hi << 16);
}
__device__ __forceinline__ uint16_t f2_to_e4m3(float a, float b){
  return (uint16_t)__nv_cvt_float2_to_fp8x2(make_float2(a, b), __NV_SATFINITE, __NV_E4M3);
}

// ---- init: x->Af8q; Af8u row64=64*bias; Af8u rows 65-127 = Rademacher;
//      Mf8 row 63 = 0 ---------------------------------------------------------
__global__ void __launch_bounds__(256) kinit(const float* __restrict__ x,
                                             const float* __restrict__ bias){
  uint32_t i = blockIdx.x*256 + threadIdx.x;     // grid 256 -> 65536
  if (i < 32768){
    float4 v = *((const float4*)x + i);
    ((uint32_t*)g_Af8q)[i] = f4_to_e4m3(v);
  }
  if (i < 512){
    float4 v = *((const float4*)bias + i);
    v.x*=WSCALE; v.y*=WSCALE; v.z*=WSCALE; v.w*=WSCALE;
    *(uint32_t*)(g_Af8u + 64*HH + i*4) = f4_to_e4m3(v);
    *(uint32_t*)(g_Mf8 + 63*HH + i*4) = 0u;
  }
  if (i < 32256){   // 63 rows x 2048 bytes of Rademacher +-1
    uint8_t o[4];
    #pragma unroll
    for (int j = 0; j < 4; j++){
      uint32_t u = i*4 + j;
      u ^= u >> 16; u *= 0x7feb352du; u ^= u >> 15; u *= 0x846ca68bu; u ^= u >> 16;
      o[j] = (u & 1u) ? 0x38u : 0xB8u;
    }
    *(uint32_t*)(g_Af8u + 65*HH + i*4) = *(uint32_t*)o;
  }
}

// ---------------- W fp32 -> e4m3 (x64): Wf8 + transposed WTf8 ----------------
__global__ void __launch_bounds__(256) kconvW(const float* __restrict__ W){
  __shared__ float s[64][65];
  int t = threadIdx.x;
  int o0 = blockIdx.y * 64, h0 = blockIdx.x * 64;
  int rr = t >> 4, c4 = t & 15;
  #pragma unroll
  for (int i = 0; i < 4; i++){
    int r = rr + i*16;
    float4 v = *(const float4*)(W + (size_t)(o0 + r)*HH + h0 + c4*4);
    v.x*=WSCALE; v.y*=WSCALE; v.z*=WSCALE; v.w*=WSCALE;
    *(uint32_t*)(g_Wf8 + (size_t)(o0 + r)*HH + h0 + c4*4) = f4_to_e4m3(v);
    s[r][c4*4+0] = v.x; s[r][c4*4+1] = v.y; s[r][c4*4+2] = v.z; s[r][c4*4+3] = v.w;
  }
  __syncthreads();
  #pragma unroll
  for (int i = 0; i < 4; i++){
    int hr = rr + i*16;
    int og = c4*4;
    float4 v = make_float4(s[og+0][hr], s[og+1][hr], s[og+2][hr], s[og+3][hr]);
    *(uint32_t*)(g_WTf8 + (size_t)(h0 + hr)*HH + o0 + og) = f4_to_e4m3(v);
  }
}

// ---- generalized fp8 GEMM mainloop: AROWS/BROWS rows, MT/NT warp tiles ------
#define GEMM_MAIN_G(Aptr, Bptr, N0, KOFF, NITER, AROWS, BROWS, MT, NT, WM, WN) \
  float acc[MT][NT][4];                                                        \
  _Pragma("unroll") for (int i = 0; i < (MT); i++)                             \
    _Pragma("unroll") for (int j = 0; j < (NT); j++)                           \
      _Pragma("unroll") for (int c = 0; c < 4; c++) acc[i][j][c] = 0.f;        \
  const uint32_t sbase = (uint32_t)__cvta_generic_to_shared(dsm);              \
  const int wm = (WM), wn = (WN);                                              \
  uint32_t soffA[(AROWS)/32], soffB[(BROWS)/32];                               \
  const uint8_t *gA[(AROWS)/32], *gB[(BROWS)/32];                              \
  _Pragma("unroll") for (int i = 0; i < (AROWS)/32; i++){                      \
    int id = t + i*256, r = id >> 3, c = id & 7;                               \
    soffA[i] = swz128((uint32_t)(r*128 + c*16));                               \
    gA[i] = (Aptr) + (size_t)r*HH + (KOFF) + c*16;                             \
  }                                                                            \
  _Pragma("unroll") for (int i = 0; i < (BROWS)/32; i++){                      \
    int id = t + i*256, r = id >> 3, c = id & 7;                               \
    soffB[i] = swz128((uint32_t)(r*128 + c*16));                               \
    gB[i] = (Bptr) + (size_t)((N0) + r)*HH + (KOFF) + c*16;                    \
  }                                                                            \
  auto issue = [&](int it){                                                    \
    if (it < (NITER)){                                                         \
      uint32_t sa = sbase + (it & 3)*((AROWS)+(BROWS))*128;                    \
      uint32_t sb = sa + (AROWS)*128;                                          \
      _Pragma("unroll") for (int i = 0; i < (AROWS)/32; i++)                   \
        cp16(sa + soffA[i], gA[i] + it*128);                                   \
      _Pragma("unroll") for (int i = 0; i < (BROWS)/32; i++)                   \
        cp16(sb + soffB[i], gB[i] + it*128);                                   \
    }                                                                          \
    cp_commit();                                                               \
  };                                                                           \
  issue(0); issue(1); issue(2);                                                \
  for (int it = 0; it < (NITER); ++it){                                        \
    issue(it + 3);                                                             \
    cp_wait<3>();                                                              \
    __syncthreads();                                                           \
    uint32_t sa = sbase + (it & 3)*((AROWS)+(BROWS))*128;                      \
    uint32_t sb = sa + (AROWS)*128;                                            \
    _Pragma("unroll") for (int ks = 0; ks < 4; ks++){                          \
      uint32_t af[MT][4], bf[NT][2];                                           \
      _Pragma("unroll") for (int mt = 0; mt < (MT); mt++){                     \
        int rr = wm + mt*16 + ((lane>>3)&1)*8 + (lane&7);                      \
        int bc = ks*32 + (lane>>4)*16;                                         \
        ldmx4(af[mt], sa + swz128((uint32_t)(rr*128 + bc)));                   \
      }                                                                        \
      _Pragma("unroll") for (int nt = 0; nt < (NT); nt++){                     \
        int rr = wn + nt*8 + (lane&7);                                         \
        int bc = ks*32 + ((lane>>3)&1)*16;                                     \
        ldmx2(bf[nt], sb + swz128((uint32_t)(rr*128 + bc)));                   \
      }                                                                        \
      _Pragma("unroll") for (int mt = 0; mt < (MT); mt++)                      \
        _Pragma("unroll") for (int nt = 0; nt < (NT); nt++)                    \
          mma16832(acc[mt][nt], af[mt], bf[nt]);                               \
    }                                                                          \
    __syncthreads();                                                           \
  }

#define QSM  (4*(64+128)*128)
#define UMSM (4*(128+128)*128)
#define SKSM (4*(128+64)*128)

// ------- Q partials: x(64 rows) @ (64W)^T, K-chunk 512 -----------------------
__global__ void __launch_bounds__(256, 1) kgemmQ(){
  extern __shared__ char dsm[];
  const int t = threadIdx.x, lane = t & 31, warp = t >> 5;
  const int n0 = blockIdx.x * 128;
  const int kc = blockIdx.y;
  GEMM_MAIN_G(g_Af8q, g_Wf8, n0, kc*512, 4, 64, 128, 2, 4,
              (warp >> 2) * 32, (warp & 3) * 32)
  const int gid = lane >> 2, tig = lane & 3;
  float* dst = g_part + (size_t)kc*64*HH;
  #pragma unroll
  for (int mt = 0; mt < 2; mt++)
    #pragma unroll
    for (int nt = 0; nt < 4; nt++){
      int row = wm + mt*16 + gid;
      int col = n0 + wn + nt*8 + tig*2;
      dst[row*HH + col]       = acc[mt][nt][0];
      dst[row*HH + col + 1]   = acc[mt][nt][1];
      dst[(row+8)*HH + col]   = acc[mt][nt][2];
      dst[(row+8)*HH + col+1] = acc[mt][nt][3];
    }
}

// ------- fixQ: sum partials, /64 + bias -> g_q fp32 + Af8u rows 0-63 ---------
__global__ void __launch_bounds__(256) kfixQ(const float* __restrict__ bias){
  uint32_t idx = (blockIdx.x*256 + threadIdx.x)*2;   // grid 256 -> 131072 elems
  int col = idx & (HH-1);
  float s0 = g_part[idx]             + g_part[64*HH + idx]
           + g_part[2*64*HH + idx]   + g_part[3*64*HH + idx];
  float s1 = g_part[idx+1]           + g_part[64*HH + idx+1]
           + g_part[2*64*HH + idx+1] + g_part[3*64*HH + idx+1];
  float q0 = s0*(1.0f/WSCALE) + bias[col];
  float q1 = s1*(1.0f/WSCALE) + bias[col+1];
  *(float2*)(g_q + idx) = make_float2(q0, q1);
  *(uint16_t*)(g_Af8u + idx) = f2_to_e4m3(q0, q1);
}

// ------- UM partials: [q; 64b; S](128 rows) @ (64W^T), K-chunk 512 -----------
__global__ void __launch_bounds__(256, 1) kgemmUM(){
  extern __shared__ char dsm[];
  const int t = threadIdx.x, lane = t & 31, warp = t >> 5;
  const int n0 = blockIdx.x * 128;
  const int kc = blockIdx.y;
  GEMM_MAIN_G(g_Af8u, g_WTf8, n0, kc*512, 4, 128, 128, 4, 4,
              (warp >> 2) * 64, (warp & 3) * 32)
  const int gid = lane >> 2, tig = lane & 3;
  float* dst = g_part + (size_t)kc*128*HH;
  #pragma unroll
  for (int mt = 0; mt < 4; mt++)
    #pragma unroll
    for (int nt = 0; nt < 4; nt++){
      int row = wm + mt*16 + gid;
      int col = n0 + wn + nt*8 + tig*2;
      dst[row*HH + col]       = acc[mt][nt][0];
      dst[row*HH + col + 1]   = acc[mt][nt][1];
      dst[(row+8)*HH + col]   = acc[mt][nt][2];
      dst[(row+8)*HH + col+1] = acc[mt][nt][3];
    }
}

// ---- fixUM: rows 65-127 -> Mf8 rows 0-62 (raw e4m3);
//      rows 0-63 -> g_uh (u = sum/64);  row 64 -> g_vh (v = sum/4096) ---------
__global__ void __launch_bounds__(256) kfixUM(){
  const uint32_t P = 128*HH;
  int bx = blockIdx.x, t = threadIdx.x;
  if (bx < 128){                        // M: 63x2048 bytes = 129024, 4/thread
    uint32_t i4 = (bx*256 + t)*4;
    if (i4 < 63*HH){
      uint32_t off = 65*HH + i4;
      float4 a = *(const float4*)(g_part + off);
      float4 b = *(const float4*)(g_part + P + off);
      float4 c = *(const float4*)(g_part + 2*P + off);
      float4 d = *(const float4*)(g_part + 3*P + off);
      float4 v = make_float4(a.x+b.x+c.x+d.x, a.y+b.y+c.y+d.y,
                             a.z+b.z+c.z+d.z, a.w+b.w+c.w+d.w);
      *(uint32_t*)(g_Mf8 + i4) = f4_to_e4m3(v);
    }
  } else if (bx < 384){                 // u: 64x2048, 2 elems/thread
    uint32_t j = ((bx-128)*256 + t)*2;
    float s0 = g_part[j]       + g_part[P + j]
             + g_part[2*P + j] + g_part[3*P + j];
    float s1 = g_part[j+1]       + g_part[P + j+1]
             + g_part[2*P + j+1] + g_part[3*P + j+1];
    *(__half2*)(g_uh + j) = __floats2half2_rn(s0*(1.0f/WSCALE), s1*(1.0f/WSCALE));
  } else {                              // v row: 2048 elems, 8/thread
    uint32_t j = t*8;
    uint32_t idx = 64*HH + j;
    float4 a = make_float4(0,0,0,0), b = make_float4(0,0,0,0);
    #pragma unroll
    for (int k = 0; k < 4; k++){
      float4 pa = *(const float4*)(g_part + k*P + idx);
      float4 pb = *(const float4*)(g_part + k*P + idx + 4);
      a.x+=pa.x; a.y+=pa.y; a.z+=pa.z; a.w+=pa.w;
      b.x+=pb.x; b.y+=pb.y; b.z+=pb.z; b.w+=pb.w;
    }
    const float sc = 1.0f/(WSCALE*WSCALE);   // v = sum/4096
    __half2 h[4];
    h[0] = __floats2half2_rn(a.x*sc, a.y*sc);
    h[1] = __floats2half2_rn(a.z*sc, a.w*sc);
    h[2] = __floats2half2_rn(b.x*sc, b.y*sc);
    h[3] = __floats2half2_rn(b.z*sc, b.w*sc);
    *(uint4*)(g_vh + j) = *(uint4*)h;
  }
}

// --- kdots fused: read KB fp32, write KBf8, dots[m]=kb.u, nadd[m]=2 kb.v -----
// CTA: same b for all 8 warps (u/v L1-resident). row = (kg*8+w)*64 + b.
__global__ void __launch_bounds__(256) kdots(const float* __restrict__ KB){
  int w = threadIdx.x >> 5, lane = threadIdx.x & 31;
  int b  = blockIdx.x >> 5;
  int kg = blockIdx.x & 31;
  int row = (kg*8 + w)*BB + b;
  const float* kp = KB + (size_t)row*HH;
  uint8_t* op = g_KBf8 + (size_t)row*HH;
  float d = 0.f, e = 0.f;
  #pragma unroll
  for (int j = 0; j < 8; j++){
    int h = j*256 + lane*8;
    float4 a  = *(const float4*)(kp + h);
    float4 a2 = *(const float4*)(kp + h + 4);
    uint2 o; o.x = f4_to_e4m3(a); o.y = f4_to_e4m3(a2);
    *(uint2*)(op + h) = o;
    uint4 uu = *(const uint4*)(g_uh + b*HH + h);
    uint4 vv = *(const uint4*)(g_vh + h);
    float2 u0 = __half22float2(*(__half2*)&uu.x);
    float2 u1 = __half22float2(*(__half2*)&uu.y);
    float2 u2 = __half22float2(*(__half2*)&uu.z);
    float2 u3 = __half22float2(*(__half2*)&uu.w);
    d += a.x*u0.x + a.y*u0.y + a.z*u1.x + a.w*u1.y
       + a2.x*u2.x + a2.y*u2.y + a2.z*u3.x + a2.w*u3.y;
    float2 v0 = __half22float2(*(__half2*)&vv.x);
    float2 v1 = __half22float2(*(__half2*)&vv.y);
    float2 v2 = __half22float2(*(__half2*)&vv.z);
    float2 v3 = __half22float2(*(__half2*)&vv.w);
    e += a.x*v0.x + a.y*v0.y + a.z*v1.x + a.w*v1.y
       + a2.x*v2.x + a2.y*v2.y + a2.z*v3.x + a2.w*v3.y;
  }
  #pragma unroll
  for (int o = 16; o; o >>= 1){
    d += __shfl_xor_sync(0xffffffffu, d, o);
    e += __shfl_xor_sync(0xffffffffu, e, o);
  }
  if (lane == 0){
    g_dots[row] = d;
    g_nadd[row] = 2.f * e;
  }
}

// --------- sketch GEMM: C = KBf8 @ Mf8^T [16384x64], rowwise sumsq -----------
__global__ void __launch_bounds__(256, 1) kgemm_sk(){
  extern __shared__ char dsm[];
  __shared__ float rowsum[128];
  const int t = threadIdx.x, lane = t & 31, warp = t >> 5;
  const int m0 = blockIdx.x * 128;
  if (t < 128) rowsum[t] = 0.f;
  GEMM_MAIN_G(g_KBf8 + (size_t)m0*HH, g_Mf8, 0, 0, 16, 128, 64, 4, 2,
              (warp >> 2) * 64, (warp & 3) * 16)
  const int gid = lane >> 2, tig = lane & 3;
  #pragma unroll
  for (int mt = 0; mt < 4; mt++){
    float s0 = 0.f, s1 = 0.f;
    #pragma unroll
    for (int nt = 0; nt < 2; nt++){
      s0 += acc[mt][nt][0]*acc[mt][nt][0] + acc[mt][nt][1]*acc[mt][nt][1];
      s1 += acc[mt][nt][2]*acc[mt][nt][2] + acc[mt][nt][3]*acc[mt][nt][3];
    }
    s0 += __shfl_xor_sync(0xffffffffu, s0, 1);
    s0 += __shfl_xor_sync(0xffffffffu, s0, 2);
    s1 += __shfl_xor_sync(0xffffffffu, s1, 1);
    s1 += __shfl_xor_sync(0xffffffffu, s1, 2);
    if (tig == 0){
      atomicAdd(&rowsum[wm + mt*16 + gid],     s0);
      atomicAdd(&rowsum[wm + mt*16 + 8 + gid], s1);
    }
  }
  __syncthreads();
  if (t < 128) g_norm2[m0 + t] = rowsum[t];
}

// ------- scores + softmax over K (q stats in-block) --------------------------
__global__ void __launch_bounds__(256) ksoftmax(const float* __restrict__ bias){
  int b = blockIdx.x, t = threadIdx.x, lane = t & 31, warp = t >> 5;
  __shared__ float sred[8], sred2[8], sred3[8];
  __shared__ float s_qn, s_qdotb, s_bn2;
  {
    const float* qr = g_q + b*HH;
    float s2 = 0.f, sb = 0.f, b2 = 0.f;
    for (int h = t; h < HH; h += 256){
      float qv = qr[h], bv = bias[h];
      s2 += qv*qv; sb += qv*bv; b2 += bv*bv;
    }
    #pragma unroll
    for (int o = 16; o; o >>= 1){
      s2 += __shfl_xor_sync(0xffffffffu, s2, o);
      sb += __shfl_xor_sync(0xffffffffu, sb, o);
      b2 += __shfl_xor_sync(0xffffffffu, b2, o);
    }
    if (lane == 0){ sred[warp] = s2; sred2[warp] = sb; sred3[warp] = b2; }
    __syncthreads();
    if (t == 0){
      float a = 0.f, c = 0.f, d = 0.f;
      #pragma unroll
      for (int i = 0; i < 8; i++){ a += sred[i]; c += sred2[i]; d += sred3[i]; }
      s_qn = fmaxf(sqrtf(a), CEPS); s_qdotb = c; s_bn2 = d;
    }
    __syncthreads();
  }
  int m = t*BB + b;
  float n2 = g_norm2[m]*SK_SCALE + g_nadd[m] + s_bn2;
  float kn = fmaxf(sqrtf(n2), CEPS);
  float sc = (g_dots[m] + s_qdotb) / (s_qn * kn);
  float v = sc;
  #pragma unroll
  for (int o = 16; o; o >>= 1) v = fmaxf(v, __shfl_xor_sync(0xffffffffu, v, o));
  __syncthreads();
  if (lane == 0) sred[warp] = v;
  __syncthreads();
  float mx = sred[0];
  #pragma unroll
  for (int i = 1; i < 8; i++) mx = fmaxf(mx, sred[i]);
  float e = expf(sc - mx);
  float s = e;
  #pragma unroll
  for (int o = 16; o; o >>= 1) s += __shfl_xor_sync(0xffffffffu, s, o);
  __syncthreads();
  if (lane == 0) sred[warp] = s;
  __syncthreads();
  float tot = 0.f;
  #pragma unroll
  for (int i = 0; i < 8; i++) tot += sred[i];
  g_attn[m] = e / tot;
}

// ------- out = x + sum_k attn[k,b] * KB[k,b,:]  (float4, 256 CTAs) -----------
__global__ void __launch_bounds__(128) kout(const float* __restrict__ x,
                                            const float* __restrict__ KB,
                                            float* __restrict__ out){
  int b = blockIdx.y;
  int h4 = blockIdx.x*128 + threadIdx.x;      // grid.x = 4
  __shared__ float at[KKN];
  at[threadIdx.x]       = g_attn[threadIdx.x*BB + b];
  at[threadIdx.x + 128] = g_attn[(threadIdx.x + 128)*BB + b];
  __syncthreads();
  const float4* p = (const float4*)KB + (size_t)b*(HH/4) + h4;
  float4 a0 = ((const float4*)x)[b*(HH/4) + h4];
  float4 a1 = make_float4(0.f,0.f,0.f,0.f);
  float4 a2 = make_float4(0.f,0.f,0.f,0.f);
  float4 a3 = make_float4(0.f,0.f,0.f,0.f);
  const size_t stride = (size_t)BB*(HH/4);
  #pragma unroll 2
  for (int k = 0; k < KKN; k += 4){
    float4 v0 = p[(k  )*stride];
    float4 v1 = p[(k+1)*stride];
    float4 v2 = p[(k+2)*stride];
    float4 v3 = p[(k+3)*stride];
    float w0 = at[k], w1 = at[k+1], w2 = at[k+2], w3 = at[k+3];
    a0.x += w0*v0.x; a0.y += w0*v0.y; a0.z += w0*v0.z; a0.w += w0*v0.w;
    a1.x += w1*v1.x; a1.y += w1*v1.y; a1.z += w1*v1.z; a1.w += w1*v1.w;
    a2.x += w2*v2.x; a2.y += w2*v2.y; a2.z += w2*v2.z; a2.w += w2*v2.w;
    a3.x += w3*v3.x; a3.y += w3*v3.y; a3.z += w3*v3.z; a3.w += w3*v3.w;
  }
  float4 r;
  r.x = a0.x + a1.x + a2.x + a3.x;
  r.y = a0.y + a1.y + a2.y + a3.y;
  r.z = a0.z + a1.z + a2.z + a3.z;
  r.w = a0.w + a1.w + a2.w + a3.w;
  ((float4*)out)[b*(HH/4) + h4] = r;
}

// ---------------- launch ------------------------------------------------------
extern "C" void kernel_launch(void* const* d_in, const int* in_sizes, int n_in,
                              void* d_out, int out_size){
  const float* x    = (const float*)d_in[0];   // [64,2048]
  const float* KB   = (const float*)d_in[1];   // [256,64,2048]
  const float* W    = (const float*)d_in[2];   // [2048,2048]
  const float* bias = (const float*)d_in[3];   // [2048]
  float* out = (float*)d_out;

  cudaFuncSetAttribute(kgemmQ,   cudaFuncAttributeMaxDynamicSharedMemorySize, QSM);
  cudaFuncSetAttribute(kgemmUM,  cudaFuncAttributeMaxDynamicSharedMemorySize, UMSM);
  cudaFuncSetAttribute(kgemm_sk, cudaFuncAttributeMaxDynamicSharedMemorySize, SKSM);

  kinit<<<256, 256>>>(x, bias);
  kconvW<<<dim3(32, 32), 256>>>(W);
  kgemmQ<<<dim3(16, 4), 256, QSM>>>();
  kfixQ<<<256, 256>>>(bias);
  kgemmUM<<<dim3(16, 4), 256, UMSM>>>();
  kfixUM<<<385, 256>>>();
  kdots<<<2048, 256>>>(KB);
  kgemm_sk<<<128, 256, SKSM>>>();
  ksoftmax<<<64, 256>>>(bias);
  kout<<<dim3(4, BB), 128>>>(x, KB, out);
}

// round 17
// speedup vs baseline: 1.3698x; 1.0333x over previous
#include <cuda_runtime.h>
#include <cuda_bf16.h>
#include <cuda_fp16.h>
#include <cuda_fp8.h>
#include <cstdint>

#define BB 64
#define HH 2048
#define KKN 256
#define MM (KKN*BB)          // 16384 rows
#define CEPS 1e-8f
#define WSCALE 64.0f
#define RSK 63               // sketch rows (packed into UM GEMM rows 65-127)
#define SK_SCALE (1.0f/258048.0f)   // 1/(RSK*WSCALE^2)

// ---------------- scratch (static device globals; no allocation) -------------
__device__ __align__(16) float g_q[BB*HH];
__device__ float g_norm2[MM];
__device__ float g_nadd[MM];
__device__ float g_dots[MM];
__device__ float g_attn[MM];
__device__ __align__(16) float g_part[8*128*HH];  // split-K partials (Q / UM)
__device__ __align__(16) __half g_uh[BB*HH];      // u in half
__device__ __align__(16) __half g_vh[HH];         // v in half
__device__ __align__(16) uint8_t g_Wf8[HH*HH];    // 64*W  [o][h]
__device__ __align__(16) uint8_t g_WTf8[HH*HH];   // 64*W^T [h][o]
__device__ __align__(16) uint8_t g_Mf8[64*HH];    // sketch M rows 0-62; row 63 = 0
__device__ __align__(16) uint8_t g_Af8q[64*HH];   // x fp8
__device__ __align__(16) uint8_t g_Af8u[128*HH];  // 0-63: q; 64: 64*bias; 65-127: S
__device__ __align__(16) uint8_t g_KBf8[(size_t)MM*HH];

// ---------------- small PTX helpers ------------------------------------------
__device__ __forceinline__ uint32_t swz128(uint32_t off){ return off ^ ((off>>3)&0x70u); }

__device__ __forceinline__ void cp16(uint32_t saddr, const void* gaddr){
  asm volatile("cp.async.cg.shared.global [%0], [%1], 16;\n" :: "r"(saddr), "l"(gaddr));
}
__device__ __forceinline__ void cp_commit(){ asm volatile("cp.async.commit_group;\n"); }
template<int N> __device__ __forceinline__ void cp_wait(){ asm volatile("cp.async.wait_group %0;\n" :: "n"(N)); }

__device__ __forceinline__ void ldmx4(uint32_t* r, uint32_t a){
  asm volatile("ldmatrix.sync.aligned.m8n8.x4.shared.b16 {%0,%1,%2,%3}, [%4];\n"
               : "=r"(r[0]), "=r"(r[1]), "=r"(r[2]), "=r"(r[3]) : "r"(a));
}
__device__ __forceinline__ void ldmx2(uint32_t* r, uint32_t a){
  asm volatile("ldmatrix.sync.aligned.m8n8.x2.shared.b16 {%0,%1}, [%2];\n"
               : "=r"(r[0]), "=r"(r[1]) : "r"(a));
}
__device__ __forceinline__ void mma16832(float* d, const uint32_t* a, const uint32_t* b){
  asm volatile("mma.sync.aligned.m16n8k32.row.col.f32.e4m3.e4m3.f32 "
               "{%0,%1,%2,%3}, {%4,%5,%6,%7}, {%8,%9}, {%0,%1,%2,%3};\n"
               : "+f"(d[0]), "+f"(d[1]), "+f"(d[2]), "+f"(d[3])
               : "r"(a[0]), "r"(a[1]), "r"(a[2]), "r"(a[3]), "r"(b[0]), "r"(b[1]));
}
__device__ __forceinline__ uint32_t f4_to_e4m3(float4 v){
  uint32_t lo = (uint32_t)__nv_cvt_float2_to_fp8x2(make_float2(v.x, v.y), __NV_SATFINITE, __NV_E4M3);
  uint32_t hi = (uint32_t)__nv_cvt_float2_to_fp8x2(make_float2(v.z, v.w), __NV_SATFINITE, __NV_E4M3);
  return lo | (hi << 16);
}
__device__ __forceinline__ uint16_t f2_to_e4m3(float a, float b){
  return (uint16_t)__nv_cvt_float2_to_fp8x2(make_float2(a, b), __NV_SATFINITE, __NV_E4M3);
}

// ---- init: x->Af8q; Af8u row64=64*bias; Af8u rows 65-127 = Rademacher;
//      Mf8 row 63 = 0 ---------------------------------------------------------
__global__ void __launch_bounds__(256) kinit(const float* __restrict__ x,
                                             const float* __restrict__ bias){
  uint32_t i = blockIdx.x*256 + threadIdx.x;     // grid 256 -> 65536
  if (i < 32768){
    float4 v = *((const float4*)x + i);
    ((uint32_t*)g_Af8q)[i] = f4_to_e4m3(v);
  }
  if (i < 512){
    float4 v = *((const float4*)bias + i);
    v.x*=WSCALE; v.y*=WSCALE; v.z*=WSCALE; v.w*=WSCALE;
    *(uint32_t*)(g_Af8u + 64*HH + i*4) = f4_to_e4m3(v);
    *(uint32_t*)(g_Mf8 + 63*HH + i*4) = 0u;
  }
  if (i < 32256){   // 63 rows x 2048 bytes of Rademacher +-1
    uint8_t o[4];
    #pragma unroll
    for (int j = 0; j < 4; j++){
      uint32_t u = i*4 + j;
      u ^= u >> 16; u *= 0x7feb352du; u ^= u >> 15; u *= 0x846ca68bu; u ^= u >> 16;
      o[j] = (u & 1u) ? 0x38u : 0xB8u;
    }
    *(uint32_t*)(g_Af8u + 65*HH + i*4) = *(uint32_t*)o;
  }
}

// ---------------- W fp32 -> e4m3 (x64): Wf8 + transposed WTf8 ----------------
__global__ void __launch_bounds__(256) kconvW(const float* __restrict__ W){
  __shared__ float s[64][65];
  int t = threadIdx.x;
  int o0 = blockIdx.y * 64, h0 = blockIdx.x * 64;
  int rr = t >> 4, c4 = t & 15;
  #pragma unroll
  for (int i = 0; i < 4; i++){
    int r = rr + i*16;
    float4 v = *(const float4*)(W + (size_t)(o0 + r)*HH + h0 + c4*4);
    v.x*=WSCALE; v.y*=WSCALE; v.z*=WSCALE; v.w*=WSCALE;
    *(uint32_t*)(g_Wf8 + (size_t)(o0 + r)*HH + h0 + c4*4) = f4_to_e4m3(v);
    s[r][c4*4+0] = v.x; s[r][c4*4+1] = v.y; s[r][c4*4+2] = v.z; s[r][c4*4+3] = v.w;
  }
  __syncthreads();
  #pragma unroll
  for (int i = 0; i < 4; i++){
    int hr = rr + i*16;
    int og = c4*4;
    float4 v = make_float4(s[og+0][hr], s[og+1][hr], s[og+2][hr], s[og+3][hr]);
    *(uint32_t*)(g_WTf8 + (size_t)(h0 + hr)*HH + o0 + og) = f4_to_e4m3(v);
  }
}

// ---- 2-stage straight-line fp8 GEMM over K-chunk 256 (2 iters of 128B) ------
#define GEMM2(Aptr, Bptr, N0, KOFF, AROWS, BROWS, MT, NT, WM, WN)              \
  float acc[MT][NT][4];                                                        \
  _Pragma("unroll") for (int i = 0; i < (MT); i++)                             \
    _Pragma("unroll") for (int j = 0; j < (NT); j++)                           \
      _Pragma("unroll") for (int c = 0; c < 4; c++) acc[i][j][c] = 0.f;        \
  const uint32_t sbase = (uint32_t)__cvta_generic_to_shared(dsm);              \
  const int wm = (WM), wn = (WN);                                              \
  uint32_t soffA[(AROWS)/32], soffB[(BROWS)/32];                               \
  const uint8_t *gA[(AROWS)/32], *gB[(BROWS)/32];                              \
  _Pragma("unroll") for (int i = 0; i < (AROWS)/32; i++){                      \
    int id = t + i*256, r = id >> 3, c = id & 7;                               \
    soffA[i] = swz128((uint32_t)(r*128 + c*16));                               \
    gA[i] = (Aptr) + (size_t)r*HH + (KOFF) + c*16;                             \
  }                                                                            \
  _Pragma("unroll") for (int i = 0; i < (BROWS)/32; i++){                      \
    int id = t + i*256, r = id >> 3, c = id & 7;                               \
    soffB[i] = swz128((uint32_t)(r*128 + c*16));                               \
    gB[i] = (Bptr) + (size_t)((N0) + r)*HH + (KOFF) + c*16;                    \
  }                                                                            \
  auto issue2 = [&](int s, int ko){                                            \
    uint32_t sa = sbase + s*((AROWS)+(BROWS))*128;                             \
    uint32_t sb = sa + (AROWS)*128;                                            \
    _Pragma("unroll") for (int i = 0; i < (AROWS)/32; i++)                     \
      cp16(sa + soffA[i], gA[i] + ko);                                         \
    _Pragma("unroll") for (int i = 0; i < (BROWS)/32; i++)                     \
      cp16(sb + soffB[i], gB[i] + ko);                                         \
    cp_commit();                                                               \
  };                                                                           \
  auto comp = [&](int s){                                                      \
    uint32_t sa = sbase + s*((AROWS)+(BROWS))*128;                             \
    uint32_t sb = sa + (AROWS)*128;                                            \
    _Pragma("unroll") for (int ks = 0; ks < 4; ks++){                          \
      uint32_t af[MT][4], bf[NT][2];                                           \
      _Pragma("unroll") for (int mt = 0; mt < (MT); mt++){                     \
        int rr = wm + mt*16 + ((lane>>3)&1)*8 + (lane&7);                      \
        int bc = ks*32 + (lane>>4)*16;                                         \
        ldmx4(af[mt], sa + swz128((uint32_t)(rr*128 + bc)));                   \
      }                                                                        \
      _Pragma("unroll") for (int nt = 0; nt < (NT); nt++){                     \
        int rr = wn + nt*8 + (lane&7);                                         \
        int bc = ks*32 + ((lane>>3)&1)*16;                                     \
        ldmx2(bf[nt], sb + swz128((uint32_t)(rr*128 + bc)));                   \
      }                                                                        \
      _Pragma("unroll") for (int mt = 0; mt < (MT); mt++)                      \
        _Pragma("unroll") for (int nt = 0; nt < (NT); nt++)                    \
          mma16832(acc[mt][nt], af[mt], bf[nt]);                               \
    }                                                                          \
  };                                                                           \
  issue2(0, 0); issue2(1, 128);                                                \
  cp_wait<1>(); __syncthreads(); comp(0);                                      \
  cp_wait<0>(); __syncthreads(); comp(1);

// ---- 4-stage generic mainloop (kept for the long-K sketch GEMM) -------------
#define GEMM_MAIN_G(Aptr, Bptr, N0, KOFF, NITER, AROWS, BROWS, MT, NT, WM, WN) \
  float acc[MT][NT][4];                                                        \
  _Pragma("unroll") for (int i = 0; i < (MT); i++)                             \
    _Pragma("unroll") for (int j = 0; j < (NT); j++)                           \
      _Pragma("unroll") for (int c = 0; c < 4; c++) acc[i][j][c] = 0.f;        \
  const uint32_t sbase = (uint32_t)__cvta_generic_to_shared(dsm);              \
  const int wm = (WM), wn = (WN);                                              \
  uint32_t soffA[(AROWS)/32], soffB[(BROWS)/32];                               \
  const uint8_t *gA[(AROWS)/32], *gB[(BROWS)/32];                              \
  _Pragma("unroll") for (int i = 0; i < (AROWS)/32; i++){                      \
    int id = t + i*256, r = id >> 3, c = id & 7;                               \
    soffA[i] = swz128((uint32_t)(r*128 + c*16));                               \
    gA[i] = (Aptr) + (size_t)r*HH + (KOFF) + c*16;                             \
  }                                                                            \
  _Pragma("unroll") for (int i = 0; i < (BROWS)/32; i++){                      \
    int id = t + i*256, r = id >> 3, c = id & 7;                               \
    soffB[i] = swz128((uint32_t)(r*128 + c*16));                               \
    gB[i] = (Bptr) + (size_t)((N0) + r)*HH + (KOFF) + c*16;                    \
  }                                                                            \
  auto issue = [&](int it){                                                    \
    if (it < (NITER)){                                                         \
      uint32_t sa = sbase + (it & 3)*((AROWS)+(BROWS))*128;                    \
      uint32_t sb = sa + (AROWS)*128;                                          \
      _Pragma("unroll") for (int i = 0; i < (AROWS)/32; i++)                   \
        cp16(sa + soffA[i], gA[i] + it*128);                                   \
      _Pragma("unroll") for (int i = 0; i < (BROWS)/32; i++)                   \
        cp16(sb + soffB[i], gB[i] + it*128);                                   \
    }                                                                          \
    cp_commit();                                                               \
  };                                                                           \
  issue(0); issue(1); issue(2);                                                \
  for (int it = 0; it < (NITER); ++it){                                        \
    issue(it + 3);                                                             \
    cp_wait<3>();                                                              \
    __syncthreads();                                                           \
    uint32_t sa = sbase + (it & 3)*((AROWS)+(BROWS))*128;                      \
    uint32_t sb = sa + (AROWS)*128;                                            \
    _Pragma("unroll") for (int ks = 0; ks < 4; ks++){                          \
      uint32_t af[MT][4], bf[NT][2];                                           \
      _Pragma("unroll") for (int mt = 0; mt < (MT); mt++){                     \
        int rr = wm + mt*16 + ((lane>>3)&1)*8 + (lane&7);                      \
        int bc = ks*32 + (lane>>4)*16;                                         \
        ldmx4(af[mt], sa + swz128((uint32_t)(rr*128 + bc)));                   \
      }                                                                        \
      _Pragma("unroll") for (int nt = 0; nt < (NT); nt++){                     \
        int rr = wn + nt*8 + (lane&7);                                         \
        int bc = ks*32 + ((lane>>3)&1)*16;                                     \
        ldmx2(bf[nt], sb + swz128((uint32_t)(rr*128 + bc)));                   \
      }                                                                        \
      _Pragma("unroll") for (int mt = 0; mt < (MT); mt++)                      \
        _Pragma("unroll") for (int nt = 0; nt < (NT); nt++)                    \
          mma16832(acc[mt][nt], af[mt], bf[nt]);                               \
    }                                                                          \
    __syncthreads();                                                           \
  }

#define QSM  (2*(64+128)*128)     // 48KB
#define UMSM (2*(128+128)*128)    // 64KB
#define SKSM (4*(128+64)*128)     // 96KB

// ------- Q partials: x(64 rows) @ (64W)^T, K-chunk 256, split-K 8 ------------
__global__ void __launch_bounds__(256, 1) kgemmQ(){
  extern __shared__ char dsm[];
  const int t = threadIdx.x, lane = t & 31, warp = t >> 5;
  const int n0 = blockIdx.x * 128;
  const int kc = blockIdx.y;
  GEMM2(g_Af8q, g_Wf8, n0, kc*256, 64, 128, 2, 4,
        (warp >> 2) * 32, (warp & 3) * 32)
  const int gid = lane >> 2, tig = lane & 3;
  float* dst = g_part + (size_t)kc*64*HH;
  #pragma unroll
  for (int mt = 0; mt < 2; mt++)
    #pragma unroll
    for (int nt = 0; nt < 4; nt++){
      int row = wm + mt*16 + gid;
      int col = n0 + wn + nt*8 + tig*2;
      dst[row*HH + col]       = acc[mt][nt][0];
      dst[row*HH + col + 1]   = acc[mt][nt][1];
      dst[(row+8)*HH + col]   = acc[mt][nt][2];
      dst[(row+8)*HH + col+1] = acc[mt][nt][3];
    }
}

// ------- fixQ: sum 8 partials, /64 + bias -> g_q fp32 + Af8u rows 0-63 -------
__global__ void __launch_bounds__(256) kfixQ(const float* __restrict__ bias){
  uint32_t idx = (blockIdx.x*256 + threadIdx.x)*2;   // grid 256 -> 131072 elems
  int col = idx & (HH-1);
  const uint32_t P = 64*HH;
  float s0 = 0.f, s1 = 0.f;
  #pragma unroll
  for (int k = 0; k < 8; k++){
    float2 p = *(const float2*)(g_part + k*P + idx);
    s0 += p.x; s1 += p.y;
  }
  float q0 = s0*(1.0f/WSCALE) + bias[col];
  float q1 = s1*(1.0f/WSCALE) + bias[col+1];
  *(float2*)(g_q + idx) = make_float2(q0, q1);
  *(uint16_t*)(g_Af8u + idx) = f2_to_e4m3(q0, q1);
}

// ------- UM partials: [q; 64b; S](128 rows) @ (64W^T), K-chunk 256 -----------
__global__ void __launch_bounds__(256, 1) kgemmUM(){
  extern __shared__ char dsm[];
  const int t = threadIdx.x, lane = t & 31, warp = t >> 5;
  const int n0 = blockIdx.x * 128;
  const int kc = blockIdx.y;
  GEMM2(g_Af8u, g_WTf8, n0, kc*256, 128, 128, 4, 4,
        (warp >> 2) * 64, (warp & 3) * 32)
  const int gid = lane >> 2, tig = lane & 3;
  float* dst = g_part + (size_t)kc*128*HH;
  #pragma unroll
  for (int mt = 0; mt < 4; mt++)
    #pragma unroll
    for (int nt = 0; nt < 4; nt++){
      int row = wm + mt*16 + gid;
      int col = n0 + wn + nt*8 + tig*2;
      dst[row*HH + col]       = acc[mt][nt][0];
      dst[row*HH + col + 1]   = acc[mt][nt][1];
      dst[(row+8)*HH + col]   = acc[mt][nt][2];
      dst[(row+8)*HH + col+1] = acc[mt][nt][3];
    }
}

// ---- fixUM: rows 65-127 -> Mf8 rows 0-62; rows 0-63 -> g_uh; row 64 -> g_vh -
__global__ void __launch_bounds__(256) kfixUM(){
  const uint32_t P = 128*HH;
  int bx = blockIdx.x, t = threadIdx.x;
  if (bx < 128){                        // M: 63x2048 bytes, 4/thread
    uint32_t i4 = (bx*256 + t)*4;
    if (i4 < 63*HH){
      uint32_t off = 65*HH + i4;
      float4 v = make_float4(0,0,0,0);
      #pragma unroll
      for (int k = 0; k < 8; k++){
        float4 p = *(const float4*)(g_part + k*P + off);
        v.x+=p.x; v.y+=p.y; v.z+=p.z; v.w+=p.w;
      }
      *(uint32_t*)(g_Mf8 + i4) = f4_to_e4m3(v);
    }
  } else if (bx < 384){                 // u: 64x2048, 2 elems/thread
    uint32_t j = ((bx-128)*256 + t)*2;
    float s0 = 0.f, s1 = 0.f;
    #pragma unroll
    for (int k = 0; k < 8; k++){
      float2 p = *(const float2*)(g_part + k*P + j);
      s0 += p.x; s1 += p.y;
    }
    *(__half2*)(g_uh + j) = __floats2half2_rn(s0*(1.0f/WSCALE), s1*(1.0f/WSCALE));
  } else {                              // v row: 2048 elems, 8/thread
    uint32_t j = t*8;
    uint32_t idx = 64*HH + j;
    float4 a = make_float4(0,0,0,0), b = make_float4(0,0,0,0);
    #pragma unroll
    for (int k = 0; k < 8; k++){
      float4 pa = *(const float4*)(g_part + k*P + idx);
      float4 pb = *(const float4*)(g_part + k*P + idx + 4);
      a.x+=pa.x; a.y+=pa.y; a.z+=pa.z; a.w+=pa.w;
      b.x+=pb.x; b.y+=pb.y; b.z+=pb.z; b.w+=pb.w;
    }
    const float sc = 1.0f/(WSCALE*WSCALE);   // v = sum/4096
    __half2 h[4];
    h[0] = __floats2half2_rn(a.x*sc, a.y*sc);
    h[1] = __floats2half2_rn(a.z*sc, a.w*sc);
    h[2] = __floats2half2_rn(b.x*sc, b.y*sc);
    h[3] = __floats2half2_rn(b.z*sc, b.w*sc);
    *(uint4*)(g_vh + j) = *(uint4*)h;
  }
}

// --- kdots fused: read KB fp32, write KBf8, dots[m]=kb.u, nadd[m]=2 kb.v -----
__global__ void __launch_bounds__(256) kdots(const float* __restrict__ KB){
  int w = threadIdx.x >> 5, lane = threadIdx.x & 31;
  int b  = blockIdx.x >> 5;
  int kg = blockIdx.x & 31;
  int row = (kg*8 + w)*BB + b;
  const float* kp = KB + (size_t)row*HH;
  uint8_t* op = g_KBf8 + (size_t)row*HH;
  float d = 0.f, e = 0.f;
  #pragma unroll
  for (int j = 0; j < 8; j++){
    int h = j*256 + lane*8;
    float4 a  = *(const float4*)(kp + h);
    float4 a2 = *(const float4*)(kp + h + 4);
    uint2 o; o.x = f4_to_e4m3(a); o.y = f4_to_e4m3(a2);
    *(uint2*)(op + h) = o;
    uint4 uu = *(const uint4*)(g_uh + b*HH + h);
    uint4 vv = *(const uint4*)(g_vh + h);
    float2 u0 = __half22float2(*(__half2*)&uu.x);
    float2 u1 = __half22float2(*(__half2*)&uu.y);
    float2 u2 = __half22float2(*(__half2*)&uu.z);
    float2 u3 = __half22float2(*(__half2*)&uu.w);
    d += a.x*u0.x + a.y*u0.y + a.z*u1.x + a.w*u1.y
       + a2.x*u2.x + a2.y*u2.y + a2.z*u3.x + a2.w*u3.y;
    float2 v0 = __half22float2(*(__half2*)&vv.x);
    float2 v1 = __half22float2(*(__half2*)&vv.y);
    float2 v2 = __half22float2(*(__half2*)&vv.z);
    float2 v3 = __half22float2(*(__half2*)&vv.w);
    e += a.x*v0.x + a.y*v0.y + a.z*v1.x + a.w*v1.y
       + a2.x*v2.x + a2.y*v2.y + a2.z*v3.x + a2.w*v3.y;
  }
  #pragma unroll
  for (int o = 16; o; o >>= 1){
    d += __shfl_xor_sync(0xffffffffu, d, o);
    e += __shfl_xor_sync(0xffffffffu, e, o);
  }
  if (lane == 0){
    g_dots[row] = d;
    g_nadd[row] = 2.f * e;
  }
}

// --------- sketch GEMM: C = KBf8 @ Mf8^T [16384x64], rowwise sumsq -----------
__global__ void __launch_bounds__(256, 1) kgemm_sk(){
  extern __shared__ char dsm[];
  __shared__ float rowsum[128];
  const int t = threadIdx.x, lane = t & 31, warp = t >> 5;
  const int m0 = blockIdx.x * 128;
  if (t < 128) rowsum[t] = 0.f;
  GEMM_MAIN_G(g_KBf8 + (size_t)m0*HH, g_Mf8, 0, 0, 16, 128, 64, 4, 2,
              (warp >> 2) * 64, (warp & 3) * 16)
  const int gid = lane >> 2, tig = lane & 3;
  #pragma unroll
  for (int mt = 0; mt < 4; mt++){
    float s0 = 0.f, s1 = 0.f;
    #pragma unroll
    for (int nt = 0; nt < 2; nt++){
      s0 += acc[mt][nt][0]*acc[mt][nt][0] + acc[mt][nt][1]*acc[mt][nt][1];
      s1 += acc[mt][nt][2]*acc[mt][nt][2] + acc[mt][nt][3]*acc[mt][nt][3];
    }
    s0 += __shfl_xor_sync(0xffffffffu, s0, 1);
    s0 += __shfl_xor_sync(0xffffffffu, s0, 2);
    s1 += __shfl_xor_sync(0xffffffffu, s1, 1);
    s1 += __shfl_xor_sync(0xffffffffu, s1, 2);
    if (tig == 0){
      atomicAdd(&rowsum[wm + mt*16 + gid],     s0);
      atomicAdd(&rowsum[wm + mt*16 + 8 + gid], s1);
    }
  }
  __syncthreads();
  if (t < 128) g_norm2[m0 + t] = rowsum[t];
}

// ------- scores + softmax over K (q stats in-block) --------------------------
__global__ void __launch_bounds__(256) ksoftmax(const float* __restrict__ bias){
  int b = blockIdx.x, t = threadIdx.x, lane = t & 31, warp = t >> 5;
  __shared__ float sred[8], sred2[8], sred3[8];
  __shared__ float s_qn, s_qdotb, s_bn2;
  {
    const float* qr = g_q + b*HH;
    float s2 = 0.f, sb = 0.f, b2 = 0.f;
    for (int h = t; h < HH; h += 256){
      float qv = qr[h], bv = bias[h];
      s2 += qv*qv; sb += qv*bv; b2 += bv*bv;
    }
    #pragma unroll
    for (int o = 16; o; o >>= 1){
      s2 += __shfl_xor_sync(0xffffffffu, s2, o);
      sb += __shfl_xor_sync(0xffffffffu, sb, o);
      b2 += __shfl_xor_sync(0xffffffffu, b2, o);
    }
    if (lane == 0){ sred[warp] = s2; sred2[warp] = sb; sred3[warp] = b2; }
    __syncthreads();
    if (t == 0){
      float a = 0.f, c = 0.f, d = 0.f;
      #pragma unroll
      for (int i = 0; i < 8; i++){ a += sred[i]; c += sred2[i]; d += sred3[i]; }
      s_qn = fmaxf(sqrtf(a), CEPS); s_qdotb = c; s_bn2 = d;
    }
    __syncthreads();
  }
  int m = t*BB + b;
  float n2 = g_norm2[m]*SK_SCALE + g_nadd[m] + s_bn2;
  float kn = fmaxf(sqrtf(n2), CEPS);
  float sc = (g_dots[m] + s_qdotb) / (s_qn * kn);
  float v = sc;
  #pragma unroll
  for (int o = 16; o; o >>= 1) v = fmaxf(v, __shfl_xor_sync(0xffffffffu, v, o));
  __syncthreads();
  if (lane == 0) sred[warp] = v;
  __syncthreads();
  float mx = sred[0];
  #pragma unroll
  for (int i = 1; i < 8; i++) mx = fmaxf(mx, sred[i]);
  float e = expf(sc - mx);
  float s = e;
  #pragma unroll
  for (int o = 16; o; o >>= 1) s += __shfl_xor_sync(0xffffffffu, s, o);
  __syncthreads();
  if (lane == 0) sred[warp] = s;
  __syncthreads();
  float tot = 0.f;
  #pragma unroll
  for (int i = 0; i < 8; i++) tot += sred[i];
  g_attn[m] = e / tot;
}

// ------- out = x + sum_k attn[k,b] * KB[k,b,:]  (float4, 256 CTAs) -----------
__global__ void __launch_bounds__(128) kout(const float* __restrict__ x,
                                            const float* __restrict__ KB,
                                            float* __restrict__ out){
  int b = blockIdx.y;
  int h4 = blockIdx.x*128 + threadIdx.x;      // grid.x = 4
  __shared__ float at[KKN];
  at[threadIdx.x]       = g_attn[threadIdx.x*BB + b];
  at[threadIdx.x + 128] = g_attn[(threadIdx.x + 128)*BB + b];
  __syncthreads();
  const float4* p = (const float4*)KB + (size_t)b*(HH/4) + h4;
  float4 a0 = ((const float4*)x)[b*(HH/4) + h4];
  float4 a1 = make_float4(0.f,0.f,0.f,0.f);
  float4 a2 = make_float4(0.f,0.f,0.f,0.f);
  float4 a3 = make_float4(0.f,0.f,0.f,0.f);
  const size_t stride = (size_t)BB*(HH/4);
  #pragma unroll 2
  for (int k = 0; k < KKN; k += 4){
    float4 v0 = p[(k  )*stride];
    float4 v1 = p[(k+1)*stride];
    float4 v2 = p[(k+2)*stride];
    float4 v3 = p[(k+3)*stride];
    float w0 = at[k], w1 = at[k+1], w2 = at[k+2], w3 = at[k+3];
    a0.x += w0*v0.x; a0.y += w0*v0.y; a0.z += w0*v0.z; a0.w += w0*v0.w;
    a1.x += w1*v1.x; a1.y += w1*v1.y; a1.z += w1*v1.z; a1.w += w1*v1.w;
    a2.x += w2*v2.x; a2.y += w2*v2.y; a2.z += w2*v2.z; a2.w += w2*v2.w;
    a3.x += w3*v3.x; a3.y += w3*v3.y; a3.z += w3*v3.z; a3.w += w3*v3.w;
  }
  float4 r;
  r.x = a0.x + a1.x + a2.x + a3.x;
  r.y = a0.y + a1.y + a2.y + a3.y;
  r.z = a0.z + a1.z + a2.z + a3.z;
  r.w = a0.w + a1.w + a2.w + a3.w;
  ((float4*)out)[b*(HH/4) + h4] = r;
}

// ---------------- launch ------------------------------------------------------
extern "C" void kernel_launch(void* const* d_in, const int* in_sizes, int n_in,
                              void* d_out, int out_size){
  const float* x    = (const float*)d_in[0];   // [64,2048]
  const float* KB   = (const float*)d_in[1];   // [256,64,2048]
  const float* W    = (const float*)d_in[2];   // [2048,2048]
  const float* bias = (const float*)d_in[3];   // [2048]
  float* out = (float*)d_out;

  cudaFuncSetAttribute(kgemmQ,   cudaFuncAttributeMaxDynamicSharedMemorySize, QSM);
  cudaFuncSetAttribute(kgemmUM,  cudaFuncAttributeMaxDynamicSharedMemorySize, UMSM);
  cudaFuncSetAttribute(kgemm_sk, cudaFuncAttributeMaxDynamicSharedMemorySize, SKSM);

  kinit<<<256, 256>>>(x, bias);
  kconvW<<<dim3(32, 32), 256>>>(W);
  kgemmQ<<<dim3(16, 8), 256, QSM>>>();
  kfixQ<<<256, 256>>>(bias);
  kgemmUM<<<dim3(16, 8), 256, UMSM>>>();
  kfixUM<<<385, 256>>>();
  kdots<<<2048, 256>>>(KB);
  kgemm_sk<<<128, 256, SKSM>>>();
  ksoftmax<<<64, 256>>>(bias);
  kout<<<dim3(4, BB), 128>>>(x, KB, out);
}